// round 9
// baseline (speedup 1.0000x reference)
#include <cuda_runtime.h>
#include <cstdint>

#define NB   2
#define SEQ  2048
#define HID  1024
#define NHD  16
#define HDD  64

// Scratch (__device__ globals; referenced only from device code)
__device__ float g_Qch[NB * NHD * SEQ * 8];   // tetra channels, score scales folded, tf32-rounded
__device__ float g_Kch[NB * NHD * SEQ * 8];
__device__ float g_V[NB * SEQ * HID];          // tf32-rounded at GEMM-0 epilogue
__device__ float g_AttOut[NB * SEQ * HID];     // tf32-rounded at attn store
__device__ float g_Xt[NB * SEQ * HID];         // tf32-rounded copy of x
__device__ float g_Wvt[HID * HID];             // tf32-rounded Wv
__device__ float g_Wot[HID * HID];             // tf32-rounded Wo

// ---------------------------------------------------------------------------
// helpers
// ---------------------------------------------------------------------------
__device__ __forceinline__ float to_tf32(float x) {
    float y;
    asm("cvt.rna.tf32.f32 %0, %1;" : "=f"(y) : "f"(x));
    return y;
}
__device__ __forceinline__ void mma_tf32(float* d, const uint32_t* a, const uint32_t* b) {
    asm volatile(
        "mma.sync.aligned.m16n8k8.row.col.f32.tf32.tf32.f32 "
        "{%0,%1,%2,%3}, {%4,%5,%6,%7}, {%8,%9}, {%0,%1,%2,%3};"
        : "+f"(d[0]), "+f"(d[1]), "+f"(d[2]), "+f"(d[3])
        : "r"(a[0]), "r"(a[1]), "r"(a[2]), "r"(a[3]), "r"(b[0]), "r"(b[1]));
}
__device__ __forceinline__ float exp_pos(float x) {   // x in [0, ~0.5]
    return 1.0f + x * (1.0f + x * (0.5f + x * (0.16666667f
           + x * (0.041666667f + x * 0.0083333333f))));
}
__device__ __forceinline__ uint32_t smem_u32(const void* p) {
    uint32_t a;
    asm("{ .reg .u64 t; cvta.to.shared.u64 t, %1; cvt.u32.u64 %0, t; }" : "=r"(a) : "l"(p));
    return a;
}
__device__ __forceinline__ void cp16(uint32_t dst, const void* src) {
    asm volatile("cp.async.ca.shared.global [%0], [%1], 16;" :: "r"(dst), "l"(src));
}
#define CP_COMMIT() asm volatile("cp.async.commit_group;" ::: "memory")
#define CP_WAIT(n)  asm volatile("cp.async.wait_group %0;" :: "n"(n) : "memory")

// ---------------------------------------------------------------------------
// Kernel 0: tf32 pre-conversion of x, Wv, Wo.
// ---------------------------------------------------------------------------
__global__ __launch_bounds__(256) void prep_convert_kernel(
    const float* __restrict__ x, const float* __restrict__ Wv, const float* __restrict__ Wo)
{
    const int n1 = NB * SEQ * HID / 4;
    const int n2 = HID * HID / 4;
    const int total = n1 + 2 * n2;
    for (int i = blockIdx.x * 256 + threadIdx.x; i < total; i += gridDim.x * 256) {
        const float4* src;
        float4* dst;
        if (i < n1)            { src = (const float4*)x  + i;            dst = (float4*)g_Xt  + i; }
        else if (i < n1 + n2)  { src = (const float4*)Wv + (i - n1);     dst = (float4*)g_Wvt + (i - n1); }
        else                   { src = (const float4*)Wo + (i - n1 - n2); dst = (float4*)g_Wot + (i - n1 - n2); }
        float4 v = *src;
        v.x = to_tf32(v.x); v.y = to_tf32(v.y); v.z = to_tf32(v.z); v.w = to_tf32(v.w);
        *dst = v;
    }
}

// ---------------------------------------------------------------------------
// Kernel 1: tetra channels for Q and K. 8 token rows per block (weight
// working set is 256KB per block regardless of rows -> more rows = less traffic).
// ---------------------------------------------------------------------------
__global__ __launch_bounds__(256) void qk_channels_kernel(
    const float* __restrict__ x,
    const float* __restrict__ Wq, const float* __restrict__ Wk,
    const float* __restrict__ bq, const float* __restrict__ bk)
{
    __shared__ float xs[8][HID];     // 32KB
    __shared__ float tvals[8][64];

    const int tid = threadIdx.x;
    const int m0  = blockIdx.x * 8;

    #pragma unroll
    for (int i = 0; i < 8; i++) {
        int idx = tid + i * 256;           // float4 id 0..2047
        int r   = idx >> 8;
        int c   = (idx & 255) * 4;
        float4 v = *(const float4*)&x[(size_t)(m0 + r) * HID + c];
        xs[r][c] = v.x; xs[r][c + 1] = v.y; xs[r][c + 2] = v.z; xs[r][c + 3] = v.w;
    }
    __syncthreads();

    const int warp = tid >> 5;
    const int lane = tid & 31;

    #pragma unroll
    for (int j = 0; j < 8; j++) {
        int d    = warp * 8 + j;           // dot index 0..63
        int qk   = d >> 5;                 // 0=Q, 1=K
        int dd   = d & 31;
        int h    = dd >> 1;
        int slot = (dd & 1) * 2;
        const float* Wrow = (qk == 0 ? Wq : Wk) + (h * HDD + slot) * HID;

        float s[8];
        #pragma unroll
        for (int r = 0; r < 8; r++) s[r] = 0.0f;
        for (int k = lane; k < HID; k += 32) {
            float wv = Wrow[k];
            #pragma unroll
            for (int r = 0; r < 8; r++) s[r] += wv * xs[r][k];
        }
        #pragma unroll
        for (int r = 0; r < 8; r++) {
            #pragma unroll
            for (int off = 16; off; off >>= 1)
                s[r] += __shfl_down_sync(0xffffffffu, s[r], off);
        }
        if (lane == 0) {
            float bias = (qk == 0 ? bq : bk)[h * HDD + slot];
            #pragma unroll
            for (int r = 0; r < 8; r++) tvals[r][d] = s[r] + bias;
        }
    }
    __syncthreads();

    #pragma unroll
    for (int ii = 0; ii < 2; ii++) {
        int idx = tid + ii * 256;
        int r  = idx >> 6;
        int d  = idx & 63;
        int m  = m0 + r;
        int b  = m / SEQ;
        int s  = m % SEQ;
        int qk = d >> 5;
        int dd = d & 31;
        int h  = dd >> 1;
        int which = dd & 1;

        float t  = tvals[r][d];
        float a  = 1.0f / (1.0f + expf(-t));
        float na = 1.0f - a;
        float nei = fminf(fmaxf(1.0f - (a + na), 0.0f), 1.0f);

        float sc = (qk == 0) ? ((which == 0) ? 0.125f : 0.1f) : 1.0f;
        float4 v;
        v.x = to_tf32(a * sc);
        v.y = to_tf32(na * sc);
        v.z = to_tf32(a * na * sc);
        v.w = to_tf32(nei * sc);
        float* dst = (qk == 0 ? g_Qch : g_Kch) + (((b * NHD + h) * SEQ + s) << 3) + which * 4;
        *(float4*)dst = v;
    }
}

// ---------------------------------------------------------------------------
// Kernel 2/4: cp.async double-buffered tf32 GEMM.  C = A @ W^T + bias.
// All inputs pre-rounded to tf32 -> raw 16B async copies, no cvt in loop.
// K-chunk 16, smem stride 20 (fragment reads conflict-free).
// mode 0: A=g_Xt,    W=g_Wvt, C=g_V (store tf32-rounded)
// mode 1: A=g_AttOut, W=g_Wot, C=Cout (plain fp32)
// ---------------------------------------------------------------------------
__global__ __launch_bounds__(256) void gemm_mma_kernel(
    const float* __restrict__ bias, float* __restrict__ Cout, int mode)
{
    const float* A = (mode == 0) ? g_Xt  : g_AttOut;
    const float* W = (mode == 0) ? g_Wvt : g_Wot;
    float*       C = (mode == 0) ? g_V   : Cout;

    __shared__ float As[2][128][20];
    __shared__ float Bs[2][128][20];

    const int tid  = threadIdx.x;
    const int lane = tid & 31;
    const int wid  = tid >> 5;
    const int bm   = blockIdx.y * 128;
    const int bn   = blockIdx.x * 128;
    const int wm   = (wid & 1) * 64;
    const int wn   = (wid >> 1) * 32;
    const int gid  = lane >> 2;
    const int tig  = lane & 3;

    const uint32_t sA = smem_u32(As);
    const uint32_t sB = smem_u32(Bs);

    // staging indices (4 cp16 per thread per chunk: 2 for A, 2 for B)
    const int srow  = tid >> 1;            // 0..127
    const int sj    = tid & 1;             // 16B chunk pair: j = sj*2, sj*2+1

    float c[4][4][4];
    #pragma unroll
    for (int mt = 0; mt < 4; mt++)
        #pragma unroll
        for (int nt = 0; nt < 4; nt++)
            #pragma unroll
            for (int k = 0; k < 4; k++) c[mt][nt][k] = 0.0f;

    // stage chunk 0 into buf 0
    {
        const float* Ap = &A[(size_t)(bm + srow) * HID + sj * 8];
        const float* Wp = &W[(size_t)(bn + srow) * HID + sj * 8];
        cp16(sA + srow * 80 + sj * 32,      Ap);
        cp16(sA + srow * 80 + sj * 32 + 16, Ap + 4);
        cp16(sB + srow * 80 + sj * 32,      Wp);
        cp16(sB + srow * 80 + sj * 32 + 16, Wp + 4);
    }
    CP_COMMIT();

    const int NCH = HID / 16;   // 64
    for (int ch = 0; ch < NCH; ch++) {
        const int buf = ch & 1;
        if (ch + 1 < NCH) {
            const int nb = (ch + 1) & 1;
            const int kc = (ch + 1) * 16;
            const float* Ap = &A[(size_t)(bm + srow) * HID + kc + sj * 8];
            const float* Wp = &W[(size_t)(bn + srow) * HID + kc + sj * 8];
            cp16(sA + nb * 10240 + srow * 80 + sj * 32,      Ap);
            cp16(sA + nb * 10240 + srow * 80 + sj * 32 + 16, Ap + 4);
            cp16(sB + nb * 10240 + srow * 80 + sj * 32,      Wp);
            cp16(sB + nb * 10240 + srow * 80 + sj * 32 + 16, Wp + 4);
            CP_COMMIT();
            CP_WAIT(1);
        } else {
            CP_WAIT(0);
        }
        __syncthreads();

        #pragma unroll
        for (int ks = 0; ks < 16; ks += 8) {
            uint32_t af[4][4];
            #pragma unroll
            for (int mt = 0; mt < 4; mt++) {
                int r0 = wm + mt * 16 + gid;
                af[mt][0] = __float_as_uint(As[buf][r0][ks + tig]);
                af[mt][1] = __float_as_uint(As[buf][r0 + 8][ks + tig]);
                af[mt][2] = __float_as_uint(As[buf][r0][ks + tig + 4]);
                af[mt][3] = __float_as_uint(As[buf][r0 + 8][ks + tig + 4]);
            }
            uint32_t bf[4][2];
            #pragma unroll
            for (int nt = 0; nt < 4; nt++) {
                int n0 = wn + nt * 8 + gid;
                bf[nt][0] = __float_as_uint(Bs[buf][n0][ks + tig]);
                bf[nt][1] = __float_as_uint(Bs[buf][n0][ks + tig + 4]);
            }
            #pragma unroll
            for (int mt = 0; mt < 4; mt++)
                #pragma unroll
                for (int nt = 0; nt < 4; nt++)
                    mma_tf32(c[mt][nt], af[mt], bf[nt]);
        }
        __syncthreads();   // buf free before it is restaged at ch+2
    }

    #pragma unroll
    for (int mt = 0; mt < 4; mt++) {
        int row0 = bm + wm + mt * 16 + gid;
        #pragma unroll
        for (int nt = 0; nt < 4; nt++) {
            int col0 = bn + wn + nt * 8 + 2 * tig;
            float b0 = bias[col0], b1 = bias[col0 + 1];
            float2 v0, v1;
            if (mode == 0) {
                v0.x = to_tf32(c[mt][nt][0] + b0); v0.y = to_tf32(c[mt][nt][1] + b1);
                v1.x = to_tf32(c[mt][nt][2] + b0); v1.y = to_tf32(c[mt][nt][3] + b1);
            } else {
                v0.x = c[mt][nt][0] + b0; v0.y = c[mt][nt][1] + b1;
                v1.x = c[mt][nt][2] + b0; v1.y = c[mt][nt][3] + b1;
            }
            *(float2*)&C[(size_t)row0 * HID + col0] = v0;
            *(float2*)&C[(size_t)(row0 + 8) * HID + col0] = v1;
        }
    }
}

// ---------------------------------------------------------------------------
// Kernel 3: tensor-core attention, cp.async double-buffered K/V tiles.
// BQ=64 q-rows per block, BK=32 key tiles.
// S phase: warps 2(m) x 4(n), warp tile 32x8 -> 2 MMAs (K=8 = full rank).
// O phase: warps 4(m) x 2(n), warp tile 16x32 -> 16 MMAs (4 k-steps x 4 n).
// ---------------------------------------------------------------------------
#define BQ 64
#define BK 32

__global__ __launch_bounds__(256) void attn_mma_kernel()
{
    __shared__ float Qs[BQ][12];
    __shared__ float Ks[2][BK][12];
    __shared__ float Vs[2][BK][72];
    __shared__ float Ps[BQ][36];
    __shared__ float z_s[BQ];

    const int tid  = threadIdx.x;
    const int lane = tid & 31;
    const int wid  = tid >> 5;
    const int gid  = lane >> 2;
    const int tig  = lane & 3;
    const int q0   = blockIdx.x * BQ;
    const int h    = blockIdx.y;
    const int b    = blockIdx.z;

    const int wmS = (wid & 1) * 32;
    const int wnS = (wid >> 1) * 8;
    const int wmO = (wid & 3) * 16;
    const int wnO = (wid >> 2) * 32;

    const float* Qg = g_Qch + (((size_t)(b * NHD + h) * SEQ + q0) << 3);
    const float* Kg = g_Kch + (((size_t)(b * NHD + h) * SEQ) << 3);
    const float* Vg = g_V + (size_t)b * SEQ * HID + h * HDD;

    const uint32_t sK = smem_u32(Ks);
    const uint32_t sV = smem_u32(Vs);

    // stage Q (64 x 8)
    if (tid < 128) {
        int r = tid >> 1, c4 = (tid & 1) * 4;
        float4 v = *(const float4*)&Qg[r * 8 + c4];
        Qs[r][c4 + 0] = v.x; Qs[r][c4 + 1] = v.y; Qs[r][c4 + 2] = v.z; Qs[r][c4 + 3] = v.w;
    }
    if (tid < BQ) z_s[tid] = 0.0f;

    // stage tile 0 into buf 0
    {
        #pragma unroll
        for (int i = 0; i < 2; i++) {
            int idx = tid + i * 256;
            int t = idx >> 4, j = idx & 15;
            cp16(sV + t * 288 + j * 16, Vg + (size_t)t * HID + j * 4);
        }
        if (tid < 64)
            cp16(sK + (tid >> 1) * 48 + (tid & 1) * 16, Kg + (tid >> 1) * 8 + (tid & 1) * 4);
    }
    CP_COMMIT();
    __syncthreads();

    // Q fragments (fixed)
    uint32_t aq[2][4];
    #pragma unroll
    for (int mt = 0; mt < 2; mt++) {
        int r0 = wmS + mt * 16 + gid;
        aq[mt][0] = __float_as_uint(Qs[r0][tig]);
        aq[mt][1] = __float_as_uint(Qs[r0 + 8][tig]);
        aq[mt][2] = __float_as_uint(Qs[r0][tig + 4]);
        aq[mt][3] = __float_as_uint(Qs[r0 + 8][tig + 4]);
    }

    float o[4][4];
    #pragma unroll
    for (int nt = 0; nt < 4; nt++)
        #pragma unroll
        for (int k = 0; k < 4; k++) o[nt][k] = 0.0f;
    float zacc[2][2] = {{0.f, 0.f}, {0.f, 0.f}};

    const int NT = SEQ / BK;   // 64
    for (int it = 0; it < NT; it++) {
        const int buf = it & 1;
        if (it + 1 < NT) {
            const int nb = (it + 1) & 1;
            const int kt = (it + 1) * BK;
            #pragma unroll
            for (int i = 0; i < 2; i++) {
                int idx = tid + i * 256;
                int t = idx >> 4, j = idx & 15;
                cp16(sV + nb * 9216 + t * 288 + j * 16, Vg + (size_t)(kt + t) * HID + j * 4);
            }
            if (tid < 64)
                cp16(sK + nb * 1536 + (tid >> 1) * 48 + (tid & 1) * 16,
                     Kg + (size_t)(kt + (tid >> 1)) * 8 + (tid & 1) * 4);
            CP_COMMIT();
            CP_WAIT(1);
        } else {
            CP_WAIT(0);
        }
        __syncthreads();

        // ---- S phase ----
        uint32_t bk_[2];
        {
            int n0 = wnS + gid;
            bk_[0] = __float_as_uint(Ks[buf][n0][tig]);
            bk_[1] = __float_as_uint(Ks[buf][n0][tig + 4]);
        }
        float c[2][4];
        #pragma unroll
        for (int mt = 0; mt < 2; mt++) {
            #pragma unroll
            for (int k = 0; k < 4; k++) c[mt][k] = 0.0f;
            mma_tf32(c[mt], aq[mt], bk_);
        }

        // exp + Ps store + z accumulate
        #pragma unroll
        for (int mt = 0; mt < 2; mt++) {
            int r  = wmS + mt * 16 + gid;
            int cc = wnS + 2 * tig;
            float e0 = exp_pos(c[mt][0]);
            float e1 = exp_pos(c[mt][1]);
            float e2 = exp_pos(c[mt][2]);
            float e3 = exp_pos(c[mt][3]);
            zacc[mt][0] += e0 + e1;
            zacc[mt][1] += e2 + e3;
            Ps[r][cc]     = to_tf32(e0);
            Ps[r][cc + 1] = to_tf32(e1);
            Ps[r + 8][cc]     = to_tf32(e2);
            Ps[r + 8][cc + 1] = to_tf32(e3);
        }
        __syncthreads();

        // ---- O phase ----
        #pragma unroll
        for (int k8 = 0; k8 < BK; k8 += 8) {
            uint32_t ap[4];
            ap[0] = __float_as_uint(Ps[wmO + gid][k8 + tig]);
            ap[1] = __float_as_uint(Ps[wmO + gid + 8][k8 + tig]);
            ap[2] = __float_as_uint(Ps[wmO + gid][k8 + tig + 4]);
            ap[3] = __float_as_uint(Ps[wmO + gid + 8][k8 + tig + 4]);
            #pragma unroll
            for (int nt = 0; nt < 4; nt++) {
                int n0 = wnO + nt * 8 + gid;
                uint32_t bv[2];
                bv[0] = __float_as_uint(Vs[buf][k8 + tig][n0]);
                bv[1] = __float_as_uint(Vs[buf][k8 + tig + 4][n0]);
                mma_tf32(o[nt], ap, bv);
            }
        }
        __syncthreads();   // Vs/Ks[buf] + Ps free before restage
    }

    // ---- Z reduction ----
    #pragma unroll
    for (int mt = 0; mt < 2; mt++)
        #pragma unroll
        for (int hf = 0; hf < 2; hf++) {
            float zv = zacc[mt][hf];
            zv += __shfl_xor_sync(0xffffffffu, zv, 1);
            zv += __shfl_xor_sync(0xffffffffu, zv, 2);
            if (tig == 0)
                atomicAdd(&z_s[wmS + mt * 16 + hf * 8 + gid], zv);
        }
    __syncthreads();

    // ---- normalize + store (tf32-rounded for GEMM-1 raw staging) ----
    const float inv0 = 1.0f / z_s[wmO + gid];
    const float inv1 = 1.0f / z_s[wmO + gid + 8];
    float* Og = g_AttOut + (size_t)(b * SEQ + q0) * HID + h * HDD;
    #pragma unroll
    for (int nt = 0; nt < 4; nt++) {
        int cc = wnO + nt * 8 + 2 * tig;
        float2 v0, v1;
        v0.x = to_tf32(o[nt][0] * inv0); v0.y = to_tf32(o[nt][1] * inv0);
        v1.x = to_tf32(o[nt][2] * inv1); v1.y = to_tf32(o[nt][3] * inv1);
        *(float2*)&Og[(size_t)(wmO + gid) * HID + cc] = v0;
        *(float2*)&Og[(size_t)(wmO + gid + 8) * HID + cc] = v1;
    }
}

// ---------------------------------------------------------------------------
extern "C" void kernel_launch(void* const* d_in, const int* in_sizes, int n_in,
                              void* d_out, int out_size)
{
    const float* x = nullptr;
    const float* Wm[4] = {nullptr, nullptr, nullptr, nullptr};
    const float* bm[4] = {nullptr, nullptr, nullptr, nullptr};
    int wi = 0, bi = 0;
    for (int i = 0; i < n_in; i++) {
        if (in_sizes[i] == NB * SEQ * HID)      x = (const float*)d_in[i];
        else if (in_sizes[i] == HID * HID) { if (wi < 4) Wm[wi++] = (const float*)d_in[i]; }
        else if (in_sizes[i] == HID)       { if (bi < 4) bm[bi++] = (const float*)d_in[i]; }
    }
    const float* Wq = Wm[0]; const float* Wk = Wm[1];
    const float* Wv = Wm[2]; const float* Wo = Wm[3];
    const float* bq = bm[0]; const float* bk = bm[1];
    const float* bv = bm[2]; const float* bo = bm[3];
    float* out = (float*)d_out;

    const int M = NB * SEQ;  // 4096

    prep_convert_kernel<<<2048, 256>>>(x, Wv, Wo);
    qk_channels_kernel<<<M / 8, 256>>>(x, Wq, Wk, bq, bk);
    {
        dim3 grid(HID / 128, M / 128);
        gemm_mma_kernel<<<grid, 256>>>(bv, nullptr, 0);
    }
    {
        dim3 grid(SEQ / BQ, NHD, NB);
        attn_mma_kernel<<<grid, 256>>>();
    }
    {
        dim3 grid(HID / 128, M / 128);
        gemm_mma_kernel<<<grid, 256>>>(bo, out, 1);
    }
}

// round 10
// speedup vs baseline: 1.9098x; 1.9098x over previous
#include <cuda_runtime.h>
#include <cstdint>

#define NB   2
#define SEQ  2048
#define HID  1024
#define NHD  16
#define HDD  64

// Scratch (allocation-free rule). Referenced ONLY from device code.
__device__ float g_Qch[NB * NHD * SEQ * 8];   // tetra channels, score scales folded in, tf32-rounded
__device__ float g_Kch[NB * NHD * SEQ * 8];
__device__ float g_V[NB * SEQ * HID];          // tf32-rounded at GEMM-0 epilogue
__device__ float g_AttOut[NB * SEQ * HID];

// ---------------------------------------------------------------------------
// mma.sync tf32 helpers (compute_103-safe)
// ---------------------------------------------------------------------------
__device__ __forceinline__ float to_tf32(float x) {
    float y;
    asm("cvt.rna.tf32.f32 %0, %1;" : "=f"(y) : "f"(x));
    return y;
}
__device__ __forceinline__ void mma_tf32(float* d, const uint32_t* a, const uint32_t* b) {
    asm volatile(
        "mma.sync.aligned.m16n8k8.row.col.f32.tf32.tf32.f32 "
        "{%0,%1,%2,%3}, {%4,%5,%6,%7}, {%8,%9}, {%0,%1,%2,%3};"
        : "+f"(d[0]), "+f"(d[1]), "+f"(d[2]), "+f"(d[3])
        : "r"(a[0]), "r"(a[1]), "r"(a[2]), "r"(a[3]), "r"(b[0]), "r"(b[1]));
}
// exp(x), x in [0, ~0.5]: degree-5 Taylor, rel err < 1.5e-5
__device__ __forceinline__ float exp_pos(float x) {
    return 1.0f + x * (1.0f + x * (0.5f + x * (0.16666667f
           + x * (0.041666667f + x * 0.0083333333f))));
}

// ---------------------------------------------------------------------------
// Kernel 1: tetra channels for Q and K (only head-dim slots 0/2 are used).
// Score scales folded into Q channels: slot0 x 0.125, slot2 x 0.1.
// Channels tf32-pre-rounded (they feed mma.sync directly).
// ---------------------------------------------------------------------------
__global__ __launch_bounds__(256) void qk_channels_kernel(
    const float* __restrict__ x,
    const float* __restrict__ Wq, const float* __restrict__ Wk,
    const float* __restrict__ bq, const float* __restrict__ bk)
{
    __shared__ float xs[4][HID];
    __shared__ float tvals[4][64];

    const int tid = threadIdx.x;
    const int m0  = blockIdx.x * 4;

    for (int i = tid; i < 4 * (HID / 4); i += 256) {
        int r = i / (HID / 4);
        int c = (i % (HID / 4)) * 4;
        float4 v = *(const float4*)&x[(m0 + r) * HID + c];
        xs[r][c] = v.x; xs[r][c + 1] = v.y; xs[r][c + 2] = v.z; xs[r][c + 3] = v.w;
    }
    __syncthreads();

    const int warp = tid >> 5;
    const int lane = tid & 31;

    #pragma unroll
    for (int j = 0; j < 8; j++) {
        int d    = warp * 8 + j;
        int qk   = d >> 5;
        int dd   = d & 31;
        int h    = dd >> 1;
        int slot = (dd & 1) * 2;
        const float* Wrow = (qk == 0 ? Wq : Wk) + (h * HDD + slot) * HID;

        float s0 = 0.f, s1 = 0.f, s2 = 0.f, s3 = 0.f;
        for (int k = lane; k < HID; k += 32) {
            float wv = Wrow[k];
            s0 += wv * xs[0][k];
            s1 += wv * xs[1][k];
            s2 += wv * xs[2][k];
            s3 += wv * xs[3][k];
        }
        #pragma unroll
        for (int off = 16; off; off >>= 1) {
            s0 += __shfl_down_sync(0xffffffffu, s0, off);
            s1 += __shfl_down_sync(0xffffffffu, s1, off);
            s2 += __shfl_down_sync(0xffffffffu, s2, off);
            s3 += __shfl_down_sync(0xffffffffu, s3, off);
        }
        if (lane == 0) {
            float bias = (qk == 0 ? bq : bk)[h * HDD + slot];
            tvals[0][d] = s0 + bias;
            tvals[1][d] = s1 + bias;
            tvals[2][d] = s2 + bias;
            tvals[3][d] = s3 + bias;
        }
    }
    __syncthreads();

    {
        int r  = tid >> 6;
        int d  = tid & 63;
        int m  = m0 + r;
        int b  = m / SEQ;
        int s  = m % SEQ;
        int qk = d >> 5;
        int dd = d & 31;
        int h  = dd >> 1;
        int which = dd & 1;

        float t  = tvals[r][d];
        float a  = 1.0f / (1.0f + expf(-t));
        float na = 1.0f - a;
        float nei = fminf(fmaxf(1.0f - (a + na), 0.0f), 1.0f);

        float sc = (qk == 0) ? ((which == 0) ? 0.125f : 0.1f) : 1.0f;
        float4 v;
        v.x = to_tf32(a * sc);
        v.y = to_tf32(na * sc);
        v.z = to_tf32(a * na * sc);
        v.w = to_tf32(nei * sc);
        float* dst = (qk == 0 ? g_Qch : g_Kch) + (((b * NHD + h) * SEQ + s) << 3) + which * 4;
        *(float4*)dst = v;
    }
}

// ---------------------------------------------------------------------------
// Kernel 2/4: mma.sync tf32 GEMM.  C[4096,1024] = A @ W^T + bias.
// Block tile 128x128, 8 warps as 2(m) x 4(n), warp tile 64x32 via m16n8k8.
// Smem tiles 128x32 with stride 36 (conflict-free fragment reads).
// mode 0: A = Ain (input x), C = g_V (stored tf32-pre-rounded for attn).
// mode 1: A = g_AttOut, C = Cout.
// ---------------------------------------------------------------------------
__global__ __launch_bounds__(256) void gemm_mma_kernel(
    const float* __restrict__ Ain, const float* __restrict__ W,
    const float* __restrict__ bias, float* __restrict__ Cout, int mode)
{
    const float* A = (mode == 0) ? Ain : (const float*)g_AttOut;
    float*       C = (mode == 0) ? g_V : Cout;

    __shared__ float As[128][36];
    __shared__ float Bs[128][36];

    const int tid  = threadIdx.x;
    const int lane = tid & 31;
    const int wid  = tid >> 5;
    const int bm   = blockIdx.y * 128;
    const int bn   = blockIdx.x * 128;
    const int wm   = (wid & 1) * 64;
    const int wn   = (wid >> 1) * 32;
    const int gid  = lane >> 2;
    const int tig  = lane & 3;

    float c[4][4][4];
    #pragma unroll
    for (int mt = 0; mt < 4; mt++)
        #pragma unroll
        for (int nt = 0; nt < 4; nt++)
            #pragma unroll
            for (int k = 0; k < 4; k++) c[mt][nt][k] = 0.0f;

    for (int kc = 0; kc < HID; kc += 32) {
        __syncthreads();
        #pragma unroll
        for (int i = 0; i < 4; i++) {
            int idx  = tid + i * 256;
            int row  = idx >> 3;
            int col4 = (idx & 7) * 4;
            float4 va = *(const float4*)&A[(size_t)(bm + row) * HID + kc + col4];
            float4 vb = *(const float4*)&W[(size_t)(bn + row) * HID + kc + col4];
            As[row][col4 + 0] = to_tf32(va.x); As[row][col4 + 1] = to_tf32(va.y);
            As[row][col4 + 2] = to_tf32(va.z); As[row][col4 + 3] = to_tf32(va.w);
            Bs[row][col4 + 0] = to_tf32(vb.x); Bs[row][col4 + 1] = to_tf32(vb.y);
            Bs[row][col4 + 2] = to_tf32(vb.z); Bs[row][col4 + 3] = to_tf32(vb.w);
        }
        __syncthreads();

        #pragma unroll
        for (int ks = 0; ks < 32; ks += 8) {
            uint32_t af[4][4];
            #pragma unroll
            for (int mt = 0; mt < 4; mt++) {
                int r0 = wm + mt * 16 + gid;
                af[mt][0] = __float_as_uint(As[r0][ks + tig]);
                af[mt][1] = __float_as_uint(As[r0 + 8][ks + tig]);
                af[mt][2] = __float_as_uint(As[r0][ks + tig + 4]);
                af[mt][3] = __float_as_uint(As[r0 + 8][ks + tig + 4]);
            }
            uint32_t bf[4][2];
            #pragma unroll
            for (int nt = 0; nt < 4; nt++) {
                int n0 = wn + nt * 8 + gid;
                bf[nt][0] = __float_as_uint(Bs[n0][ks + tig]);
                bf[nt][1] = __float_as_uint(Bs[n0][ks + tig + 4]);
            }
            #pragma unroll
            for (int mt = 0; mt < 4; mt++)
                #pragma unroll
                for (int nt = 0; nt < 4; nt++)
                    mma_tf32(c[mt][nt], af[mt], bf[nt]);
        }
    }

    #pragma unroll
    for (int mt = 0; mt < 4; mt++) {
        int row0 = bm + wm + mt * 16 + gid;
        #pragma unroll
        for (int nt = 0; nt < 4; nt++) {
            int col0 = bn + wn + nt * 8 + 2 * tig;
            float b0 = bias[col0], b1 = bias[col0 + 1];
            float2 v0, v1;
            if (mode == 0) {
                // pre-round V to tf32 so attention stages it raw (no cvt)
                v0.x = to_tf32(c[mt][nt][0] + b0); v0.y = to_tf32(c[mt][nt][1] + b1);
                v1.x = to_tf32(c[mt][nt][2] + b0); v1.y = to_tf32(c[mt][nt][3] + b1);
            } else {
                v0.x = c[mt][nt][0] + b0; v0.y = c[mt][nt][1] + b1;
                v1.x = c[mt][nt][2] + b0; v1.y = c[mt][nt][3] + b1;
            }
            *(float2*)&C[(size_t)row0 * HID + col0] = v0;
            *(float2*)&C[(size_t)(row0 + 8) * HID + col0] = v1;
        }
    }
}

// ---------------------------------------------------------------------------
// Kernel 3: tensor-core attention (round-6 structure, BK=64).
// Block = (b, h, 64 q-rows); iterates 64-key tiles.
// S-tile = ONE m16n8k8 tf32 MMA per 16x8 tile (rank-8 trick, K=8).
// exp in registers, P routed via smem (tf32) to re-fragment for P.V.
// V staged RAW (g_V is tf32-pre-rounded by GEMM-0).
// S-phase warps: 2(m) x 4(n), warp tile 32x16.
// O-phase warps: 4(m) x 2(n), warp tile 16x32.
// ---------------------------------------------------------------------------
#define BQ 64
#define BK 64

__global__ __launch_bounds__(256) void attn_mma_kernel()
{
    __shared__ float Qs[BQ][12];   // stride 12: (12*gid+tig)%32 all distinct
    __shared__ float Ks[BK][12];
    __shared__ float Ps[BQ][68];   // stride 68: (4*gid+tig)%32 all distinct
    __shared__ float Vs[BK][72];   // stride 72: (8*tig+gid)%32 all distinct
    __shared__ float z_s[BQ];

    const int tid  = threadIdx.x;
    const int lane = tid & 31;
    const int wid  = tid >> 5;
    const int gid  = lane >> 2;
    const int tig  = lane & 3;
    const int q0   = blockIdx.x * BQ;
    const int h    = blockIdx.y;
    const int b    = blockIdx.z;

    const int wmS = (wid & 1) * 32;   // S-phase m offset
    const int wnS = (wid >> 1) * 16;  // S-phase n offset
    const int wmO = (wid & 3) * 16;   // O-phase m offset
    const int wnO = (wid >> 2) * 32;  // O-phase n offset

    const float* Qg = g_Qch + (((size_t)(b * NHD + h) * SEQ + q0) << 3);
    const float* Kg = g_Kch + (((size_t)(b * NHD + h) * SEQ) << 3);
    const float* Vg = g_V + (size_t)b * SEQ * HID + h * HDD;

    // stage Q tile (64 rows x 8 ch)
    if (tid < 128) {
        int r = tid >> 1, c4 = (tid & 1) * 4;
        float4 v = *(const float4*)&Qg[r * 8 + c4];
        Qs[r][c4 + 0] = v.x; Qs[r][c4 + 1] = v.y; Qs[r][c4 + 2] = v.z; Qs[r][c4 + 3] = v.w;
    }
    __syncthreads();

    // Q A-fragments (fixed for whole kernel)
    uint32_t aq[2][4];
    #pragma unroll
    for (int mt = 0; mt < 2; mt++) {
        int r0 = wmS + mt * 16 + gid;
        aq[mt][0] = __float_as_uint(Qs[r0][tig]);
        aq[mt][1] = __float_as_uint(Qs[r0 + 8][tig]);
        aq[mt][2] = __float_as_uint(Qs[r0][tig + 4]);
        aq[mt][3] = __float_as_uint(Qs[r0 + 8][tig + 4]);
    }

    float o[4][4];
    #pragma unroll
    for (int nt = 0; nt < 4; nt++)
        #pragma unroll
        for (int k = 0; k < 4; k++) o[nt][k] = 0.0f;
    float zacc[2][2] = {{0.f, 0.f}, {0.f, 0.f}};

    for (int kt = 0; kt < SEQ; kt += BK) {
        __syncthreads();   // prev O-phase done with Ks/Vs
        // stage K channels (64 x 8) — already tf32
        if (tid < 128) {
            int r = tid >> 1, c4 = (tid & 1) * 4;
            float4 v = *(const float4*)&Kg[((size_t)kt) * 8 + r * 8 + c4];
            Ks[r][c4 + 0] = v.x; Ks[r][c4 + 1] = v.y; Ks[r][c4 + 2] = v.z; Ks[r][c4 + 3] = v.w;
        }
        // stage V tile (64 x 64) — already tf32, raw copy
        #pragma unroll
        for (int i = 0; i < 4; i++) {
            int idx = tid + i * 256;
            int t   = idx >> 4;
            int d4  = (idx & 15) * 4;
            float4 v = *(const float4*)&Vg[(size_t)(kt + t) * HID + d4];
            Vs[t][d4 + 0] = v.x; Vs[t][d4 + 1] = v.y;
            Vs[t][d4 + 2] = v.z; Vs[t][d4 + 3] = v.w;
        }
        __syncthreads();

        // ---- S phase: 4 MMAs (K=8 = full rank) ----
        uint32_t bk_[2][2];
        #pragma unroll
        for (int nt = 0; nt < 2; nt++) {
            int n0 = wnS + nt * 8 + gid;
            bk_[nt][0] = __float_as_uint(Ks[n0][tig]);
            bk_[nt][1] = __float_as_uint(Ks[n0][tig + 4]);
        }
        float c[2][2][4];
        #pragma unroll
        for (int mt = 0; mt < 2; mt++)
            #pragma unroll
            for (int nt = 0; nt < 2; nt++) {
                #pragma unroll
                for (int k = 0; k < 4; k++) c[mt][nt][k] = 0.0f;
                mma_tf32(c[mt][nt], aq[mt], bk_[nt]);
            }

        // exp + store P (tf32) to smem, accumulate z
        #pragma unroll
        for (int mt = 0; mt < 2; mt++) {
            int r = wmS + mt * 16 + gid;
            #pragma unroll
            for (int nt = 0; nt < 2; nt++) {
                int cc = wnS + nt * 8 + 2 * tig;
                float e0 = exp_pos(c[mt][nt][0]);
                float e1 = exp_pos(c[mt][nt][1]);
                float e2 = exp_pos(c[mt][nt][2]);
                float e3 = exp_pos(c[mt][nt][3]);
                zacc[mt][0] += e0 + e1;
                zacc[mt][1] += e2 + e3;
                Ps[r][cc]     = to_tf32(e0);
                Ps[r][cc + 1] = to_tf32(e1);
                Ps[r + 8][cc]     = to_tf32(e2);
                Ps[r + 8][cc + 1] = to_tf32(e3);
            }
        }
        __syncthreads();

        // ---- O phase: P(64xBK) @ V(BKx64), 8 k-steps x 4 n-tiles ----
        #pragma unroll
        for (int k8 = 0; k8 < BK; k8 += 8) {
            uint32_t ap[4];
            ap[0] = __float_as_uint(Ps[wmO + gid][k8 + tig]);
            ap[1] = __float_as_uint(Ps[wmO + gid + 8][k8 + tig]);
            ap[2] = __float_as_uint(Ps[wmO + gid][k8 + tig + 4]);
            ap[3] = __float_as_uint(Ps[wmO + gid + 8][k8 + tig + 4]);
            #pragma unroll
            for (int nt = 0; nt < 4; nt++) {
                int n0 = wnO + nt * 8 + gid;
                uint32_t bv[2];
                bv[0] = __float_as_uint(Vs[k8 + tig][n0]);
                bv[1] = __float_as_uint(Vs[k8 + tig + 4][n0]);
                mma_tf32(o[nt], ap, bv);
            }
        }
    }

    // ---- Z reduction ----
    __syncthreads();
    if (tid < BQ) z_s[tid] = 0.0f;
    __syncthreads();
    #pragma unroll
    for (int mt = 0; mt < 2; mt++)
        #pragma unroll
        for (int hf = 0; hf < 2; hf++) {
            float zv = zacc[mt][hf];
            zv += __shfl_xor_sync(0xffffffffu, zv, 1);
            zv += __shfl_xor_sync(0xffffffffu, zv, 2);
            if (tig == 0)
                atomicAdd(&z_s[wmS + mt * 16 + hf * 8 + gid], zv);
        }
    __syncthreads();

    // ---- normalize + store ----
    const float inv0 = 1.0f / z_s[wmO + gid];
    const float inv1 = 1.0f / z_s[wmO + gid + 8];
    float* Og = g_AttOut + (size_t)(b * SEQ + q0) * HID + h * HDD;
    #pragma unroll
    for (int nt = 0; nt < 4; nt++) {
        int cc = wnO + nt * 8 + 2 * tig;
        float2 v0; v0.x = o[nt][0] * inv0; v0.y = o[nt][1] * inv0;
        float2 v1; v1.x = o[nt][2] * inv1; v1.y = o[nt][3] * inv1;
        *(float2*)&Og[(size_t)(wmO + gid) * HID + cc] = v0;
        *(float2*)&Og[(size_t)(wmO + gid + 8) * HID + cc] = v1;
    }
}

// ---------------------------------------------------------------------------
extern "C" void kernel_launch(void* const* d_in, const int* in_sizes, int n_in,
                              void* d_out, int out_size)
{
    const float* x = nullptr;
    const float* Wm[4] = {nullptr, nullptr, nullptr, nullptr};
    const float* bm[4] = {nullptr, nullptr, nullptr, nullptr};
    int wi = 0, bi = 0;
    for (int i = 0; i < n_in; i++) {
        if (in_sizes[i] == NB * SEQ * HID)      x = (const float*)d_in[i];
        else if (in_sizes[i] == HID * HID) { if (wi < 4) Wm[wi++] = (const float*)d_in[i]; }
        else if (in_sizes[i] == HID)       { if (bi < 4) bm[bi++] = (const float*)d_in[i]; }
    }
    const float* Wq = Wm[0]; const float* Wk = Wm[1];
    const float* Wv = Wm[2]; const float* Wo = Wm[3];
    const float* bq = bm[0]; const float* bk = bm[1];
    const float* bv = bm[2]; const float* bo = bm[3];
    float* out = (float*)d_out;

    const int M = NB * SEQ;  // 4096

    qk_channels_kernel<<<M / 4, 256>>>(x, Wq, Wk, bq, bk);
    {
        dim3 grid(HID / 128, M / 128);
        gemm_mma_kernel<<<grid, 256>>>(x, Wv, bv, nullptr, 0);
    }
    {
        dim3 grid(SEQ / BQ, NHD, NB);
        attn_mma_kernel<<<grid, 256>>>();
    }
    {
        dim3 grid(HID / 128, M / 128);
        gemm_mma_kernel<<<grid, 256>>>(nullptr, Wo, bo, out, 1);
    }
}

// round 11
// speedup vs baseline: 2.7162x; 1.4223x over previous
#include <cuda_runtime.h>
#include <cuda_fp16.h>
#include <cstdint>

#define NB   2
#define SEQ  2048
#define HID  1024
#define NHD  16
#define HDD  64

// Scratch (allocation-free rule). Referenced ONLY from device code.
// Channels/V/AttOut now fp16 (packed half2 as uint32).
__device__ uint32_t g_Qch[NB * NHD * SEQ * 4];  // [token][4 half2] (8 channels)
__device__ uint32_t g_Kch[NB * NHD * SEQ * 4];
__device__ uint32_t g_Vp[(NB * SEQ / 2) * HID]; // row-PAIR packed: [pair][dim] = (V[2p][d], V[2p+1][d])
__device__ __half   g_AttOut[NB * SEQ * HID];   // plain row-major half

// ---------------------------------------------------------------------------
// helpers
// ---------------------------------------------------------------------------
__device__ __forceinline__ uint32_t pack_h2(float lo, float hi) {
    __half2 h = __floats2half2_rn(lo, hi);
    return *(uint32_t*)&h;
}
__device__ __forceinline__ void mma_f16_k16(float* d, const uint32_t* a, const uint32_t* b) {
    asm volatile(
        "mma.sync.aligned.m16n8k16.row.col.f32.f16.f16.f32 "
        "{%0,%1,%2,%3}, {%4,%5,%6,%7}, {%8,%9}, {%0,%1,%2,%3};"
        : "+f"(d[0]), "+f"(d[1]), "+f"(d[2]), "+f"(d[3])
        : "r"(a[0]), "r"(a[1]), "r"(a[2]), "r"(a[3]), "r"(b[0]), "r"(b[1]));
}
__device__ __forceinline__ void mma_f16_k8(float* d, const uint32_t* a, const uint32_t* b) {
    asm volatile(
        "mma.sync.aligned.m16n8k8.row.col.f32.f16.f16.f32 "
        "{%0,%1,%2,%3}, {%4,%5}, {%6}, {%0,%1,%2,%3};"
        : "+f"(d[0]), "+f"(d[1]), "+f"(d[2]), "+f"(d[3])
        : "r"(a[0]), "r"(a[1]), "r"(b[0]));
}
// exp(x), x in [0, ~0.5]: degree-5 Taylor, rel err < 1.5e-5
__device__ __forceinline__ float exp_pos(float x) {
    return 1.0f + x * (1.0f + x * (0.5f + x * (0.16666667f
           + x * (0.041666667f + x * 0.0083333333f))));
}

// ---------------------------------------------------------------------------
// Kernel 1: tetra channels for Q and K (only head-dim slots 0/2 are used).
// Score scales folded into Q channels. Output packed half2.
// ---------------------------------------------------------------------------
__global__ __launch_bounds__(256) void qk_channels_kernel(
    const float* __restrict__ x,
    const float* __restrict__ Wq, const float* __restrict__ Wk,
    const float* __restrict__ bq, const float* __restrict__ bk)
{
    __shared__ float xs[4][HID];
    __shared__ float tvals[4][64];

    const int tid = threadIdx.x;
    const int m0  = blockIdx.x * 4;

    for (int i = tid; i < 4 * (HID / 4); i += 256) {
        int r = i / (HID / 4);
        int c = (i % (HID / 4)) * 4;
        float4 v = *(const float4*)&x[(m0 + r) * HID + c];
        xs[r][c] = v.x; xs[r][c + 1] = v.y; xs[r][c + 2] = v.z; xs[r][c + 3] = v.w;
    }
    __syncthreads();

    const int warp = tid >> 5;
    const int lane = tid & 31;

    #pragma unroll
    for (int j = 0; j < 8; j++) {
        int d    = warp * 8 + j;
        int qk   = d >> 5;
        int dd   = d & 31;
        int h    = dd >> 1;
        int slot = (dd & 1) * 2;
        const float* Wrow = (qk == 0 ? Wq : Wk) + (h * HDD + slot) * HID;

        float s0 = 0.f, s1 = 0.f, s2 = 0.f, s3 = 0.f;
        for (int k = lane; k < HID; k += 32) {
            float wv = Wrow[k];
            s0 += wv * xs[0][k];
            s1 += wv * xs[1][k];
            s2 += wv * xs[2][k];
            s3 += wv * xs[3][k];
        }
        #pragma unroll
        for (int off = 16; off; off >>= 1) {
            s0 += __shfl_down_sync(0xffffffffu, s0, off);
            s1 += __shfl_down_sync(0xffffffffu, s1, off);
            s2 += __shfl_down_sync(0xffffffffu, s2, off);
            s3 += __shfl_down_sync(0xffffffffu, s3, off);
        }
        if (lane == 0) {
            float bias = (qk == 0 ? bq : bk)[h * HDD + slot];
            tvals[0][d] = s0 + bias;
            tvals[1][d] = s1 + bias;
            tvals[2][d] = s2 + bias;
            tvals[3][d] = s3 + bias;
        }
    }
    __syncthreads();

    {
        int r  = tid >> 6;
        int d  = tid & 63;
        int m  = m0 + r;
        int b  = m / SEQ;
        int s  = m % SEQ;
        int qk = d >> 5;
        int dd = d & 31;
        int h  = dd >> 1;
        int which = dd & 1;

        float t  = tvals[r][d];
        float a  = 1.0f / (1.0f + expf(-t));
        float na = 1.0f - a;
        float nei = fminf(fmaxf(1.0f - (a + na), 0.0f), 1.0f);

        float sc = (qk == 0) ? ((which == 0) ? 0.125f : 0.1f) : 1.0f;
        uint32_t* dst = (qk == 0 ? g_Qch : g_Kch)
                        + ((size_t)(b * NHD + h) * SEQ + s) * 4 + which * 2;
        dst[0] = pack_h2(a * sc, na * sc);
        dst[1] = pack_h2(a * na * sc, nei * sc);
    }
}

// ---------------------------------------------------------------------------
// Kernel 2/4: fp16 mma GEMM (m16n8k16).  C[4096,1024] = A @ W^T + bias.
// Block tile 128x128, warps 2(m) x 4(n), warp tile 64x32.
// Smem: half2 tiles [128][20] uint32 (stride 20 -> conflict-free fragments).
// mode 0: A = x (fp32), C -> g_Vp in row-pair half2 layout.
// mode 1: A = g_AttOut (half), C -> Cout fp32.
// ---------------------------------------------------------------------------
__global__ __launch_bounds__(256) void gemm_mma_kernel(
    const float* __restrict__ Ain, const float* __restrict__ W,
    const float* __restrict__ bias, float* __restrict__ Cout, int mode)
{
    __shared__ uint32_t As[128][20];   // 16 half2 used per row
    __shared__ uint32_t Bs[128][20];

    const int tid  = threadIdx.x;
    const int lane = tid & 31;
    const int wid  = tid >> 5;
    const int bm   = blockIdx.y * 128;
    const int bn   = blockIdx.x * 128;
    const int wm   = (wid & 1) * 64;
    const int wn   = (wid >> 1) * 32;
    const int gid  = lane >> 2;
    const int tig  = lane & 3;

    float c[4][4][4];
    #pragma unroll
    for (int mt = 0; mt < 4; mt++)
        #pragma unroll
        for (int nt = 0; nt < 4; nt++)
            #pragma unroll
            for (int k = 0; k < 4; k++) c[mt][nt][k] = 0.0f;

    for (int kc = 0; kc < HID; kc += 32) {
        __syncthreads();
        #pragma unroll
        for (int i = 0; i < 4; i++) {
            int idx  = tid + i * 256;      // 0..1023
            int row  = idx >> 3;
            int c8   = (idx & 7);          // which group of 4 floats/halves
            // B (weights) always fp32 -> cvt
            float4 vb = *(const float4*)&W[(size_t)(bn + row) * HID + kc + c8 * 4];
            Bs[row][c8 * 2]     = pack_h2(vb.x, vb.y);
            Bs[row][c8 * 2 + 1] = pack_h2(vb.z, vb.w);
            if (mode == 0) {
                float4 va = *(const float4*)&Ain[(size_t)(bm + row) * HID + kc + c8 * 4];
                As[row][c8 * 2]     = pack_h2(va.x, va.y);
                As[row][c8 * 2 + 1] = pack_h2(va.z, va.w);
            } else {
                uint2 va = *(const uint2*)&g_AttOut[(size_t)(bm + row) * HID + kc + c8 * 4];
                As[row][c8 * 2]     = va.x;
                As[row][c8 * 2 + 1] = va.y;
            }
        }
        __syncthreads();

        #pragma unroll
        for (int ks2 = 0; ks2 < 16; ks2 += 8) {   // half2 base: k16 step
            uint32_t af[4][4];
            #pragma unroll
            for (int mt = 0; mt < 4; mt++) {
                int r0 = wm + mt * 16 + gid;
                af[mt][0] = As[r0][ks2 + tig];
                af[mt][1] = As[r0 + 8][ks2 + tig];
                af[mt][2] = As[r0][ks2 + tig + 4];
                af[mt][3] = As[r0 + 8][ks2 + tig + 4];
            }
            uint32_t bf[4][2];
            #pragma unroll
            for (int nt = 0; nt < 4; nt++) {
                int n0 = wn + nt * 8 + gid;
                bf[nt][0] = Bs[n0][ks2 + tig];
                bf[nt][1] = Bs[n0][ks2 + tig + 4];
            }
            #pragma unroll
            for (int mt = 0; mt < 4; mt++)
                #pragma unroll
                for (int nt = 0; nt < 4; nt++)
                    mma_f16_k16(c[mt][nt], af[mt], bf[nt]);
        }
    }

    if (mode == 0) {
        // pack row-pairs (2p, 2p+1) into half2 for attention's V B-fragments
        #pragma unroll
        for (int mt = 0; mt < 4; mt++) {
            int rbase = bm + wm + mt * 16 + (gid & ~1);
            int p0 = rbase >> 1;
            #pragma unroll
            for (int nt = 0; nt < 4; nt++) {
                int col0 = bn + wn + nt * 8 + 2 * tig;
                float b0 = bias[col0], b1 = bias[col0 + 1];
                float v0 = c[mt][nt][0] + b0;
                float v1 = c[mt][nt][1] + b1;
                float v2 = c[mt][nt][2] + b0;
                float v3 = c[mt][nt][3] + b1;
                float o0 = __shfl_xor_sync(0xffffffffu, v0, 4);
                float o1 = __shfl_xor_sync(0xffffffffu, v1, 4);
                float o2 = __shfl_xor_sync(0xffffffffu, v2, 4);
                float o3 = __shfl_xor_sync(0xffffffffu, v3, 4);
                if ((gid & 1) == 0) {
                    g_Vp[(size_t)p0 * HID + col0]       = pack_h2(v0, o0);
                    g_Vp[(size_t)(p0 + 4) * HID + col0] = pack_h2(v2, o2);
                } else {
                    g_Vp[(size_t)p0 * HID + col0 + 1]       = pack_h2(o1, v1);
                    g_Vp[(size_t)(p0 + 4) * HID + col0 + 1] = pack_h2(o3, v3);
                }
            }
        }
    } else {
        #pragma unroll
        for (int mt = 0; mt < 4; mt++) {
            int row0 = bm + wm + mt * 16 + gid;
            #pragma unroll
            for (int nt = 0; nt < 4; nt++) {
                int col0 = bn + wn + nt * 8 + 2 * tig;
                float b0 = bias[col0], b1 = bias[col0 + 1];
                float2 v0; v0.x = c[mt][nt][0] + b0; v0.y = c[mt][nt][1] + b1;
                float2 v1; v1.x = c[mt][nt][2] + b0; v1.y = c[mt][nt][3] + b1;
                *(float2*)&Cout[(size_t)row0 * HID + col0] = v0;
                *(float2*)&Cout[(size_t)(row0 + 8) * HID + col0] = v1;
            }
        }
    }
}

// ---------------------------------------------------------------------------
// Kernel 3: fp16 tensor-core attention (BK=64).
// S phase: m16n8k8.f16 (rank-8, 1 mma per 16x8 tile); warps 2(m) x 4(n).
// O phase: m16n8k16.f16, V pre-packed row-pair layout; warps 4(m) x 2(n).
// ---------------------------------------------------------------------------
#define BQ 64
#define BK 64

__global__ __launch_bounds__(256) void attn_mma_kernel()
{
    __shared__ uint32_t Qs[BQ][4];    // [token][4 half2]; banks 4*gid+tig distinct
    __shared__ uint32_t Ks[BK][4];
    __shared__ uint32_t Ps[BQ][36];   // [row][32 half2 + pad]; banks 4*gid+tig
    __shared__ uint32_t Vs[BK / 2][72]; // [token-pair][64 dims + pad]; banks 8*t2+d
    __shared__ float z_s[BQ];

    const int tid  = threadIdx.x;
    const int lane = tid & 31;
    const int wid  = tid >> 5;
    const int gid  = lane >> 2;
    const int tig  = lane & 3;
    const int q0   = blockIdx.x * BQ;
    const int h    = blockIdx.y;
    const int b    = blockIdx.z;

    const int wmS = (wid & 1) * 32;   // S-phase m offset
    const int wnS = (wid >> 1) * 16;  // S-phase n offset
    const int wmO = (wid & 3) * 16;   // O-phase m offset
    const int wnO = (wid >> 2) * 32;  // O-phase n offset

    const uint32_t* Qg = g_Qch + ((size_t)(b * NHD + h) * SEQ + q0) * 4;
    const uint32_t* Kg = g_Kch + ((size_t)(b * NHD + h) * SEQ) * 4;
    const uint32_t* Vg = g_Vp + (size_t)b * (SEQ / 2) * HID + h * HDD;

    // stage Q tile (64 tokens x 4 half2 = 256 u32)
    ((uint32_t*)Qs)[tid] = Qg[tid];
    if (tid < BQ) z_s[tid] = 0.0f;
    __syncthreads();

    // Q A-fragments (m16n8k8: 2 regs), fixed for whole kernel
    uint32_t aq[2][2];
    #pragma unroll
    for (int mt = 0; mt < 2; mt++) {
        int r0 = wmS + mt * 16 + gid;
        aq[mt][0] = Qs[r0][tig];
        aq[mt][1] = Qs[r0 + 8][tig];
    }

    float o[4][4];
    #pragma unroll
    for (int nt = 0; nt < 4; nt++)
        #pragma unroll
        for (int k = 0; k < 4; k++) o[nt][k] = 0.0f;
    float zacc[2][2] = {{0.f, 0.f}, {0.f, 0.f}};

    for (int kt = 0; kt < SEQ; kt += BK) {
        __syncthreads();   // prev O-phase done with Ks/Vs
        // stage K (64 tokens x 4 half2 = 256 u32)
        ((uint32_t*)Ks)[tid] = Kg[kt * 4 + tid];
        // stage V tile: 32 pairs x 64 half2 = 2048 u32, raw coalesced copy
        #pragma unroll
        for (int i = 0; i < 8; i++) {
            int idx = tid + i * 256;
            int t2  = idx >> 6;
            int d   = idx & 63;
            Vs[t2][d] = Vg[(size_t)(kt / 2 + t2) * HID + d];
        }
        __syncthreads();

        // ---- S phase: m16n8k8 f16, 4 MMAs per warp ----
        uint32_t bk_[2];
        #pragma unroll
        for (int nt = 0; nt < 2; nt++)
            bk_[nt] = Ks[wnS + nt * 8 + gid][tig];
        float c[2][2][4];
        #pragma unroll
        for (int mt = 0; mt < 2; mt++)
            #pragma unroll
            for (int nt = 0; nt < 2; nt++) {
                #pragma unroll
                for (int k = 0; k < 4; k++) c[mt][nt][k] = 0.0f;
                mma_f16_k8(c[mt][nt], aq[mt], &bk_[nt]);
            }

        // exp + store P (half2) to smem, accumulate z
        #pragma unroll
        for (int mt = 0; mt < 2; mt++) {
            int r = wmS + mt * 16 + gid;
            #pragma unroll
            for (int nt = 0; nt < 2; nt++) {
                int cc2 = (wnS >> 1) + nt * 4 + tig;
                float e0 = exp_pos(c[mt][nt][0]);
                float e1 = exp_pos(c[mt][nt][1]);
                float e2 = exp_pos(c[mt][nt][2]);
                float e3 = exp_pos(c[mt][nt][3]);
                zacc[mt][0] += e0 + e1;
                zacc[mt][1] += e2 + e3;
                Ps[r][cc2]     = pack_h2(e0, e1);
                Ps[r + 8][cc2] = pack_h2(e2, e3);
            }
        }
        __syncthreads();

        // ---- O phase: P(64x64) @ V(64x64), m16n8k16, 4 ksteps x 4 nt ----
        #pragma unroll
        for (int kst = 0; kst < 4; kst++) {
            const int k2 = kst * 8;   // half2 base within P row / V pair rows
            uint32_t ap[4];
            ap[0] = Ps[wmO + gid][k2 + tig];
            ap[1] = Ps[wmO + gid + 8][k2 + tig];
            ap[2] = Ps[wmO + gid][k2 + tig + 4];
            ap[3] = Ps[wmO + gid + 8][k2 + tig + 4];
            #pragma unroll
            for (int nt = 0; nt < 4; nt++) {
                int n0 = wnO + nt * 8 + gid;
                uint32_t bv[2];
                bv[0] = Vs[k2 + tig][n0];
                bv[1] = Vs[k2 + tig + 4][n0];
                mma_f16_k16(o[nt], ap, bv);
            }
        }
    }

    // ---- Z reduction ----
    __syncthreads();
    #pragma unroll
    for (int mt = 0; mt < 2; mt++)
        #pragma unroll
        for (int hf = 0; hf < 2; hf++) {
            float zv = zacc[mt][hf];
            zv += __shfl_xor_sync(0xffffffffu, zv, 1);
            zv += __shfl_xor_sync(0xffffffffu, zv, 2);
            if (tig == 0)
                atomicAdd(&z_s[wmS + mt * 16 + hf * 8 + gid], zv);
        }
    __syncthreads();

    // ---- normalize + store (half, plain row-major for GEMM-1) ----
    const float inv0 = 1.0f / z_s[wmO + gid];
    const float inv1 = 1.0f / z_s[wmO + gid + 8];
    uint32_t* Og = (uint32_t*)g_AttOut;   // half2 view, HID/2 per row
    const size_t rowbase = (size_t)(b * SEQ + q0);
    #pragma unroll
    for (int nt = 0; nt < 4; nt++) {
        int cc2 = (h * HDD + wnO + nt * 8 + 2 * tig) >> 1;
        Og[(rowbase + wmO + gid) * (HID / 2) + cc2] =
            pack_h2(o[nt][0] * inv0, o[nt][1] * inv0);
        Og[(rowbase + wmO + gid + 8) * (HID / 2) + cc2] =
            pack_h2(o[nt][2] * inv1, o[nt][3] * inv1);
    }
}

// ---------------------------------------------------------------------------
extern "C" void kernel_launch(void* const* d_in, const int* in_sizes, int n_in,
                              void* d_out, int out_size)
{
    const float* x = nullptr;
    const float* Wm[4] = {nullptr, nullptr, nullptr, nullptr};
    const float* bm[4] = {nullptr, nullptr, nullptr, nullptr};
    int wi = 0, bi = 0;
    for (int i = 0; i < n_in; i++) {
        if (in_sizes[i] == NB * SEQ * HID)      x = (const float*)d_in[i];
        else if (in_sizes[i] == HID * HID) { if (wi < 4) Wm[wi++] = (const float*)d_in[i]; }
        else if (in_sizes[i] == HID)       { if (bi < 4) bm[bi++] = (const float*)d_in[i]; }
    }
    const float* Wq = Wm[0]; const float* Wk = Wm[1];
    const float* Wv = Wm[2]; const float* Wo = Wm[3];
    const float* bq = bm[0]; const float* bk = bm[1];
    const float* bv = bm[2]; const float* bo = bm[3];
    float* out = (float*)d_out;

    const int M = NB * SEQ;  // 4096

    qk_channels_kernel<<<M / 4, 256>>>(x, Wq, Wk, bq, bk);
    {
        dim3 grid(HID / 128, M / 128);
        gemm_mma_kernel<<<grid, 256>>>(x, Wv, bv, nullptr, 0);
    }
    {
        dim3 grid(SEQ / BQ, NHD, NB);
        attn_mma_kernel<<<grid, 256>>>();
    }
    {
        dim3 grid(HID / 128, M / 128);
        gemm_mma_kernel<<<grid, 256>>>(nullptr, Wo, bo, out, 1);
    }
}

// round 13
// speedup vs baseline: 2.8711x; 1.0570x over previous
#include <cuda_runtime.h>
#include <cuda_fp16.h>
#include <cstdint>

#define NB   2
#define SEQ  2048
#define HID  1024
#define NHD  16
#define HDD  64

// Scratch (allocation-free rule). Referenced ONLY from device code.
__device__ uint32_t g_Qch[NB * NHD * SEQ * 4];  // [token][4 half2] (8 channels)
__device__ uint32_t g_Kch[NB * NHD * SEQ * 4];
__device__ uint32_t g_Vp[(NB * SEQ / 2) * HID]; // row-PAIR packed half2
__device__ __half   g_AttOut[NB * SEQ * HID];   // plain row-major half

// ---------------------------------------------------------------------------
// helpers
// ---------------------------------------------------------------------------
__device__ __forceinline__ uint32_t pack_h2(float lo, float hi) {
    __half2 h = __floats2half2_rn(lo, hi);
    return *(uint32_t*)&h;
}
__device__ __forceinline__ void mma_f16_k16(float* d, const uint32_t* a, const uint32_t* b) {
    asm volatile(
        "mma.sync.aligned.m16n8k16.row.col.f32.f16.f16.f32 "
        "{%0,%1,%2,%3}, {%4,%5,%6,%7}, {%8,%9}, {%0,%1,%2,%3};"
        : "+f"(d[0]), "+f"(d[1]), "+f"(d[2]), "+f"(d[3])
        : "r"(a[0]), "r"(a[1]), "r"(a[2]), "r"(a[3]), "r"(b[0]), "r"(b[1]));
}
__device__ __forceinline__ void mma_f16_k8(float* d, const uint32_t* a, const uint32_t* b) {
    asm volatile(
        "mma.sync.aligned.m16n8k8.row.col.f32.f16.f16.f32 "
        "{%0,%1,%2,%3}, {%4,%5}, {%6}, {%0,%1,%2,%3};"
        : "+f"(d[0]), "+f"(d[1]), "+f"(d[2]), "+f"(d[3])
        : "r"(a[0]), "r"(a[1]), "r"(b[0]));
}
// exp(x), x in [0, ~0.5]: degree-5 Taylor, rel err < 1.5e-5
__device__ __forceinline__ float exp_pos(float x) {
    return 1.0f + x * (1.0f + x * (0.5f + x * (0.16666667f
           + x * (0.041666667f + x * 0.0083333333f))));
}

// ---------------------------------------------------------------------------
// Kernel 1: QK projection as fp16 mma GEMM + tetra-channel epilogue.
// C[4096, 64] = x @ Wqk^T ; dot index d: qk=d>>5, dd=d&31, h=dd>>1,
// slot=(dd&1)*2. Block tile 32(m) x 64(n=all dots), K chunks of 64.
// Warps: 2(m) x 4(n), warp tile 16x16.
// ---------------------------------------------------------------------------
#define QK_BM 32

__global__ __launch_bounds__(256) void qk_mma_kernel(
    const float* __restrict__ x,
    const float* __restrict__ Wq, const float* __restrict__ Wk,
    const float* __restrict__ bq, const float* __restrict__ bk)
{
    __shared__ uint32_t As[QK_BM][36];   // 32 half2 per row used
    __shared__ uint32_t Ws[64][36];

    const int tid  = threadIdx.x;
    const int lane = tid & 31;
    const int wid  = tid >> 5;
    const int gid  = lane >> 2;
    const int tig  = lane & 3;
    const int bm   = blockIdx.x * QK_BM;
    const int wm   = (wid & 1) * 16;
    const int wn   = (wid >> 1) * 16;

    float c[2][4];
    #pragma unroll
    for (int nt = 0; nt < 2; nt++)
        #pragma unroll
        for (int k = 0; k < 4; k++) c[nt][k] = 0.0f;

    for (int kc = 0; kc < HID; kc += 64) {
        __syncthreads();
        // stage A: 32 rows x 16 float4
        #pragma unroll
        for (int i = 0; i < 2; i++) {
            int idx = tid + i * 256;
            int row = idx >> 4;
            int c8  = idx & 15;
            float4 v = *(const float4*)&x[(size_t)(bm + row) * HID + kc + c8 * 4];
            *(uint2*)&As[row][c8 * 2] = make_uint2(pack_h2(v.x, v.y), pack_h2(v.z, v.w));
        }
        // stage W: 64 dot rows x 16 float4 (gather from Wq/Wk rows)
        #pragma unroll
        for (int i = 0; i < 4; i++) {
            int idx = tid + i * 256;
            int row = idx >> 4;           // dot index 0..63
            int c8  = idx & 15;
            int qk   = row >> 5;
            int dd   = row & 31;
            int h    = dd >> 1;
            int slot = (dd & 1) * 2;
            const float* Wr = (qk ? Wk : Wq) + (size_t)(h * HDD + slot) * HID;
            float4 v = *(const float4*)&Wr[kc + c8 * 4];
            *(uint2*)&Ws[row][c8 * 2] = make_uint2(pack_h2(v.x, v.y), pack_h2(v.z, v.w));
        }
        __syncthreads();

        #pragma unroll
        for (int ks2 = 0; ks2 < 32; ks2 += 8) {
            uint32_t af[4];
            int r0 = wm + gid;
            af[0] = As[r0][ks2 + tig];
            af[1] = As[r0 + 8][ks2 + tig];
            af[2] = As[r0][ks2 + tig + 4];
            af[3] = As[r0 + 8][ks2 + tig + 4];
            #pragma unroll
            for (int nt = 0; nt < 2; nt++) {
                int n0 = wn + nt * 8 + gid;
                uint32_t bf[2];
                bf[0] = Ws[n0][ks2 + tig];
                bf[1] = Ws[n0][ks2 + tig + 4];
                mma_f16_k16(c[nt], af, bf);
            }
        }
    }

    // epilogue: per thread 2 col-pairs x 2 rows -> full channel quads
    #pragma unroll
    for (int nt = 0; nt < 2; nt++) {
        int col0 = wn + nt * 8 + 2 * tig;   // even
        int qk = col0 >> 5;
        int dd = col0 & 31;
        int h  = dd >> 1;
        const float* bb = qk ? bk : bq;
        float b0 = bb[h * HDD + 0];
        float b1 = bb[h * HDD + 2];
        float sc0 = (qk == 0) ? 0.125f : 1.0f;
        float sc1 = (qk == 0) ? 0.1f   : 1.0f;
        #pragma unroll
        for (int hf = 0; hf < 2; hf++) {
            int m = bm + wm + gid + hf * 8;
            float t0 = c[nt][hf * 2 + 0] + b0;
            float t1 = c[nt][hf * 2 + 1] + b1;

            float a0 = 1.0f / (1.0f + expf(-t0));
            float na0 = 1.0f - a0;
            float nei0 = fminf(fmaxf(1.0f - (a0 + na0), 0.0f), 1.0f);
            float a1 = 1.0f / (1.0f + expf(-t1));
            float na1 = 1.0f - a1;
            float nei1 = fminf(fmaxf(1.0f - (a1 + na1), 0.0f), 1.0f);

            uint4 out;
            out.x = pack_h2(a0 * sc0, na0 * sc0);
            out.y = pack_h2(a0 * na0 * sc0, nei0 * sc0);
            out.z = pack_h2(a1 * sc1, na1 * sc1);
            out.w = pack_h2(a1 * na1 * sc1, nei1 * sc1);

            int b_ = m / SEQ;
            int s_ = m % SEQ;
            uint32_t* dst = (qk ? g_Kch : g_Qch) + ((size_t)(b_ * NHD + h) * SEQ + s_) * 4;
            *(uint4*)dst = out;
        }
    }
}

// ---------------------------------------------------------------------------
// Kernel 2/4: fp16 mma GEMM (m16n8k16), double-buffered + register prefetch.
// One __syncthreads per K-chunk; LDG for chunk c+1 overlaps mma on chunk c.
// mode 0: A = x (fp32), C -> g_Vp row-pair half2.  mode 1: A = g_AttOut, C fp32.
// ---------------------------------------------------------------------------
__global__ __launch_bounds__(256) void gemm_mma_kernel(
    const float* __restrict__ Ain, const float* __restrict__ W,
    const float* __restrict__ bias, float* __restrict__ Cout, int mode)
{
    __shared__ uint32_t As[2][128][20];
    __shared__ uint32_t Bs[2][128][20];

    const int tid  = threadIdx.x;
    const int lane = tid & 31;
    const int wid  = tid >> 5;
    const int bm   = blockIdx.y * 128;
    const int bn   = blockIdx.x * 128;
    const int wm   = (wid & 1) * 64;
    const int wn   = (wid >> 1) * 32;
    const int gid  = lane >> 2;
    const int tig  = lane & 3;

    float c[4][4][4];
    #pragma unroll
    for (int mt = 0; mt < 4; mt++)
        #pragma unroll
        for (int nt = 0; nt < 4; nt++)
            #pragma unroll
            for (int k = 0; k < 4; k++) c[mt][nt][k] = 0.0f;

    float4 rb[4];
    float4 raf[4];   // mode 0
    uint2  rah[4];   // mode 1

    const int NCH = HID / 32;   // 32 chunks

    // prologue: load chunk 0 -> regs -> smem buf 0
    #pragma unroll
    for (int i = 0; i < 4; i++) {
        int idx = tid + i * 256;
        int row = idx >> 3;
        int c8  = idx & 7;
        rb[i] = *(const float4*)&W[(size_t)(bn + row) * HID + c8 * 4];
        if (mode == 0) raf[i] = *(const float4*)&Ain[(size_t)(bm + row) * HID + c8 * 4];
        else           rah[i] = *(const uint2*)&g_AttOut[(size_t)(bm + row) * HID + c8 * 4];
    }
    #pragma unroll
    for (int i = 0; i < 4; i++) {
        int idx = tid + i * 256;
        int row = idx >> 3;
        int c8  = idx & 7;
        *(uint2*)&Bs[0][row][c8 * 2] = make_uint2(pack_h2(rb[i].x, rb[i].y), pack_h2(rb[i].z, rb[i].w));
        if (mode == 0)
            *(uint2*)&As[0][row][c8 * 2] = make_uint2(pack_h2(raf[i].x, raf[i].y), pack_h2(raf[i].z, raf[i].w));
        else
            *(uint2*)&As[0][row][c8 * 2] = rah[i];
    }
    __syncthreads();

    for (int ch = 0; ch < NCH; ch++) {
        const int buf = ch & 1;
        const bool more = (ch + 1 < NCH);
        if (more) {
            const int kc = (ch + 1) * 32;
            #pragma unroll
            for (int i = 0; i < 4; i++) {
                int idx = tid + i * 256;
                int row = idx >> 3;
                int c8  = idx & 7;
                rb[i] = *(const float4*)&W[(size_t)(bn + row) * HID + kc + c8 * 4];
                if (mode == 0) raf[i] = *(const float4*)&Ain[(size_t)(bm + row) * HID + kc + c8 * 4];
                else           rah[i] = *(const uint2*)&g_AttOut[(size_t)(bm + row) * HID + kc + c8 * 4];
            }
        }

        #pragma unroll
        for (int ks2 = 0; ks2 < 16; ks2 += 8) {
            uint32_t af[4][4];
            #pragma unroll
            for (int mt = 0; mt < 4; mt++) {
                int r0 = wm + mt * 16 + gid;
                af[mt][0] = As[buf][r0][ks2 + tig];
                af[mt][1] = As[buf][r0 + 8][ks2 + tig];
                af[mt][2] = As[buf][r0][ks2 + tig + 4];
                af[mt][3] = As[buf][r0 + 8][ks2 + tig + 4];
            }
            uint32_t bf[4][2];
            #pragma unroll
            for (int nt = 0; nt < 4; nt++) {
                int n0 = wn + nt * 8 + gid;
                bf[nt][0] = Bs[buf][n0][ks2 + tig];
                bf[nt][1] = Bs[buf][n0][ks2 + tig + 4];
            }
            #pragma unroll
            for (int mt = 0; mt < 4; mt++)
                #pragma unroll
                for (int nt = 0; nt < 4; nt++)
                    mma_f16_k16(c[mt][nt], af[mt], bf[nt]);
        }

        if (more) {
            const int nb = buf ^ 1;
            #pragma unroll
            for (int i = 0; i < 4; i++) {
                int idx = tid + i * 256;
                int row = idx >> 3;
                int c8  = idx & 7;
                *(uint2*)&Bs[nb][row][c8 * 2] = make_uint2(pack_h2(rb[i].x, rb[i].y), pack_h2(rb[i].z, rb[i].w));
                if (mode == 0)
                    *(uint2*)&As[nb][row][c8 * 2] = make_uint2(pack_h2(raf[i].x, raf[i].y), pack_h2(raf[i].z, raf[i].w));
                else
                    *(uint2*)&As[nb][row][c8 * 2] = rah[i];
            }
        }
        __syncthreads();
    }

    if (mode == 0) {
        // pack row-pairs (2p, 2p+1) into half2 for attention's V B-fragments
        #pragma unroll
        for (int mt = 0; mt < 4; mt++) {
            int rbase = bm + wm + mt * 16 + (gid & ~1);
            int p0 = rbase >> 1;
            #pragma unroll
            for (int nt = 0; nt < 4; nt++) {
                int col0 = bn + wn + nt * 8 + 2 * tig;
                float b0 = bias[col0], b1 = bias[col0 + 1];
                float v0 = c[mt][nt][0] + b0;
                float v1 = c[mt][nt][1] + b1;
                float v2 = c[mt][nt][2] + b0;
                float v3 = c[mt][nt][3] + b1;
                float o0 = __shfl_xor_sync(0xffffffffu, v0, 4);
                float o1 = __shfl_xor_sync(0xffffffffu, v1, 4);
                float o2 = __shfl_xor_sync(0xffffffffu, v2, 4);
                float o3 = __shfl_xor_sync(0xffffffffu, v3, 4);
                if ((gid & 1) == 0) {
                    g_Vp[(size_t)p0 * HID + col0]       = pack_h2(v0, o0);
                    g_Vp[(size_t)(p0 + 4) * HID + col0] = pack_h2(v2, o2);
                } else {
                    g_Vp[(size_t)p0 * HID + col0 + 1]       = pack_h2(o1, v1);
                    g_Vp[(size_t)(p0 + 4) * HID + col0 + 1] = pack_h2(o3, v3);
                }
            }
        }
    } else {
        #pragma unroll
        for (int mt = 0; mt < 4; mt++) {
            int row0 = bm + wm + mt * 16 + gid;
            #pragma unroll
            for (int nt = 0; nt < 4; nt++) {
                int col0 = bn + wn + nt * 8 + 2 * tig;
                float b0 = bias[col0], b1 = bias[col0 + 1];
                float2 v0; v0.x = c[mt][nt][0] + b0; v0.y = c[mt][nt][1] + b1;
                float2 v1; v1.x = c[mt][nt][2] + b0; v1.y = c[mt][nt][3] + b1;
                *(float2*)&Cout[(size_t)row0 * HID + col0] = v0;
                *(float2*)&Cout[(size_t)(row0 + 8) * HID + col0] = v1;
            }
        }
    }
}

// ---------------------------------------------------------------------------
// Kernel 3: fp16 tensor-core attention (unchanged from round 11).
// ---------------------------------------------------------------------------
#define BQ 64
#define BK 64

__global__ __launch_bounds__(256) void attn_mma_kernel()
{
    __shared__ uint32_t Qs[BQ][4];
    __shared__ uint32_t Ks[BK][4];
    __shared__ uint32_t Ps[BQ][36];
    __shared__ uint32_t Vs[BK / 2][72];
    __shared__ float z_s[BQ];

    const int tid  = threadIdx.x;
    const int lane = tid & 31;
    const int wid  = tid >> 5;
    const int gid  = lane >> 2;
    const int tig  = lane & 3;
    const int q0   = blockIdx.x * BQ;
    const int h    = blockIdx.y;
    const int b    = blockIdx.z;

    const int wmS = (wid & 1) * 32;
    const int wnS = (wid >> 1) * 16;
    const int wmO = (wid & 3) * 16;
    const int wnO = (wid >> 2) * 32;

    const uint32_t* Qg = g_Qch + ((size_t)(b * NHD + h) * SEQ + q0) * 4;
    const uint32_t* Kg = g_Kch + ((size_t)(b * NHD + h) * SEQ) * 4;
    const uint32_t* Vg = g_Vp + (size_t)b * (SEQ / 2) * HID + h * HDD;

    ((uint32_t*)Qs)[tid] = Qg[tid];
    if (tid < BQ) z_s[tid] = 0.0f;
    __syncthreads();

    uint32_t aq[2][2];
    #pragma unroll
    for (int mt = 0; mt < 2; mt++) {
        int r0 = wmS + mt * 16 + gid;
        aq[mt][0] = Qs[r0][tig];
        aq[mt][1] = Qs[r0 + 8][tig];
    }

    float o[4][4];
    #pragma unroll
    for (int nt = 0; nt < 4; nt++)
        #pragma unroll
        for (int k = 0; k < 4; k++) o[nt][k] = 0.0f;
    float zacc[2][2] = {{0.f, 0.f}, {0.f, 0.f}};

    for (int kt = 0; kt < SEQ; kt += BK) {
        __syncthreads();
        ((uint32_t*)Ks)[tid] = Kg[kt * 4 + tid];
        #pragma unroll
        for (int i = 0; i < 8; i++) {
            int idx = tid + i * 256;
            int t2  = idx >> 6;
            int d   = idx & 63;
            Vs[t2][d] = Vg[(size_t)(kt / 2 + t2) * HID + d];
        }
        __syncthreads();

        uint32_t bk_[2];
        #pragma unroll
        for (int nt = 0; nt < 2; nt++)
            bk_[nt] = Ks[wnS + nt * 8 + gid][tig];
        float c[2][2][4];
        #pragma unroll
        for (int mt = 0; mt < 2; mt++)
            #pragma unroll
            for (int nt = 0; nt < 2; nt++) {
                #pragma unroll
                for (int k = 0; k < 4; k++) c[mt][nt][k] = 0.0f;
                mma_f16_k8(c[mt][nt], aq[mt], &bk_[nt]);
            }

        #pragma unroll
        for (int mt = 0; mt < 2; mt++) {
            int r = wmS + mt * 16 + gid;
            #pragma unroll
            for (int nt = 0; nt < 2; nt++) {
                int cc2 = (wnS >> 1) + nt * 4 + tig;
                float e0 = exp_pos(c[mt][nt][0]);
                float e1 = exp_pos(c[mt][nt][1]);
                float e2 = exp_pos(c[mt][nt][2]);
                float e3 = exp_pos(c[mt][nt][3]);
                zacc[mt][0] += e0 + e1;
                zacc[mt][1] += e2 + e3;
                Ps[r][cc2]     = pack_h2(e0, e1);
                Ps[r + 8][cc2] = pack_h2(e2, e3);
            }
        }
        __syncthreads();

        #pragma unroll
        for (int kst = 0; kst < 4; kst++) {
            const int k2 = kst * 8;
            uint32_t ap[4];
            ap[0] = Ps[wmO + gid][k2 + tig];
            ap[1] = Ps[wmO + gid + 8][k2 + tig];
            ap[2] = Ps[wmO + gid][k2 + tig + 4];
            ap[3] = Ps[wmO + gid + 8][k2 + tig + 4];
            #pragma unroll
            for (int nt = 0; nt < 4; nt++) {
                int n0 = wnO + nt * 8 + gid;
                uint32_t bv[2];
                bv[0] = Vs[k2 + tig][n0];
                bv[1] = Vs[k2 + tig + 4][n0];
                mma_f16_k16(o[nt], ap, bv);
            }
        }
    }

    __syncthreads();
    #pragma unroll
    for (int mt = 0; mt < 2; mt++)
        #pragma unroll
        for (int hf = 0; hf < 2; hf++) {
            float zv = zacc[mt][hf];
            zv += __shfl_xor_sync(0xffffffffu, zv, 1);
            zv += __shfl_xor_sync(0xffffffffu, zv, 2);
            if (tig == 0)
                atomicAdd(&z_s[wmS + mt * 16 + hf * 8 + gid], zv);
        }
    __syncthreads();

    const float inv0 = 1.0f / z_s[wmO + gid];
    const float inv1 = 1.0f / z_s[wmO + gid + 8];
    uint32_t* Og = (uint32_t*)g_AttOut;
    const size_t rowbase = (size_t)(b * SEQ + q0);
    #pragma unroll
    for (int nt = 0; nt < 4; nt++) {
        int cc2 = (h * HDD + wnO + nt * 8 + 2 * tig) >> 1;
        Og[(rowbase + wmO + gid) * (HID / 2) + cc2] =
            pack_h2(o[nt][0] * inv0, o[nt][1] * inv0);
        Og[(rowbase + wmO + gid + 8) * (HID / 2) + cc2] =
            pack_h2(o[nt][2] * inv1, o[nt][3] * inv1);
    }
}

// ---------------------------------------------------------------------------
extern "C" void kernel_launch(void* const* d_in, const int* in_sizes, int n_in,
                              void* d_out, int out_size)
{
    const float* x = nullptr;
    const float* Wm[4] = {nullptr, nullptr, nullptr, nullptr};
    const float* bm[4] = {nullptr, nullptr, nullptr, nullptr};
    int wi = 0, bi = 0;
    for (int i = 0; i < n_in; i++) {
        if (in_sizes[i] == NB * SEQ * HID)      x = (const float*)d_in[i];
        else if (in_sizes[i] == HID * HID) { if (wi < 4) Wm[wi++] = (const float*)d_in[i]; }
        else if (in_sizes[i] == HID)       { if (bi < 4) bm[bi++] = (const float*)d_in[i]; }
    }
    const float* Wq = Wm[0]; const float* Wk = Wm[1];
    const float* Wv = Wm[2]; const float* Wo = Wm[3];
    const float* bq = bm[0]; const float* bk = bm[1];
    const float* bv = bm[2]; const float* bo = bm[3];
    float* out = (float*)d_out;

    const int M = NB * SEQ;  // 4096

    qk_mma_kernel<<<M / QK_BM, 256>>>(x, Wq, Wk, bq, bk);
    {
        dim3 grid(HID / 128, M / 128);
        gemm_mma_kernel<<<grid, 256>>>(x, Wv, bv, nullptr, 0);
    }
    {
        dim3 grid(SEQ / BQ, NHD, NB);
        attn_mma_kernel<<<grid, 256>>>();
    }
    {
        dim3 grid(HID / 128, M / 128);
        gemm_mma_kernel<<<grid, 256>>>(nullptr, Wo, bo, out, 1);
    }
}

// round 14
// speedup vs baseline: 3.2936x; 1.1472x over previous
#include <cuda_runtime.h>
#include <cuda_fp16.h>
#include <cstdint>

#define NB   2
#define SEQ  2048
#define HID  1024
#define NHD  16
#define HDD  64

// Scratch (allocation-free rule). Referenced ONLY from device code.
__device__ uint32_t g_Qch[NB * NHD * SEQ * 4];  // [token][4 half2] (8 channels)
__device__ uint32_t g_Kch[NB * NHD * SEQ * 4];
__device__ uint32_t g_Vp[(NB * SEQ / 2) * HID]; // row-PAIR packed half2
__device__ __half   g_AttOut[NB * SEQ * HID];   // plain row-major half

// ---------------------------------------------------------------------------
// helpers
// ---------------------------------------------------------------------------
__device__ __forceinline__ uint32_t pack_h2(float lo, float hi) {
    __half2 h = __floats2half2_rn(lo, hi);
    return *(uint32_t*)&h;
}
__device__ __forceinline__ void mma_f16_k16(float* d, const uint32_t* a, const uint32_t* b) {
    asm volatile(
        "mma.sync.aligned.m16n8k16.row.col.f32.f16.f16.f32 "
        "{%0,%1,%2,%3}, {%4,%5,%6,%7}, {%8,%9}, {%0,%1,%2,%3};"
        : "+f"(d[0]), "+f"(d[1]), "+f"(d[2]), "+f"(d[3])
        : "r"(a[0]), "r"(a[1]), "r"(a[2]), "r"(a[3]), "r"(b[0]), "r"(b[1]));
}
__device__ __forceinline__ void mma_f16_k8(float* d, const uint32_t* a, const uint32_t* b) {
    asm volatile(
        "mma.sync.aligned.m16n8k8.row.col.f32.f16.f16.f32 "
        "{%0,%1,%2,%3}, {%4,%5}, {%6}, {%0,%1,%2,%3};"
        : "+f"(d[0]), "+f"(d[1]), "+f"(d[2]), "+f"(d[3])
        : "r"(a[0]), "r"(a[1]), "r"(b[0]));
}
// exp(x), x in [0, ~0.5]: degree-5 Taylor, rel err < 1.5e-5
__device__ __forceinline__ float exp_pos(float x) {
    return 1.0f + x * (1.0f + x * (0.5f + x * (0.16666667f
           + x * (0.041666667f + x * 0.0083333333f))));
}

// ---------------------------------------------------------------------------
// Kernel 1: QK projection as fp16 mma GEMM + tetra-channel epilogue.
// (verified WIN in round 13: ~12 us)
// ---------------------------------------------------------------------------
#define QK_BM 32

__global__ __launch_bounds__(256) void qk_mma_kernel(
    const float* __restrict__ x,
    const float* __restrict__ Wq, const float* __restrict__ Wk,
    const float* __restrict__ bq, const float* __restrict__ bk)
{
    __shared__ uint32_t As[QK_BM][36];
    __shared__ uint32_t Ws[64][36];

    const int tid  = threadIdx.x;
    const int lane = tid & 31;
    const int wid  = tid >> 5;
    const int gid  = lane >> 2;
    const int tig  = lane & 3;
    const int bm   = blockIdx.x * QK_BM;
    const int wm   = (wid & 1) * 16;
    const int wn   = (wid >> 1) * 16;

    float c[2][4];
    #pragma unroll
    for (int nt = 0; nt < 2; nt++)
        #pragma unroll
        for (int k = 0; k < 4; k++) c[nt][k] = 0.0f;

    for (int kc = 0; kc < HID; kc += 64) {
        __syncthreads();
        #pragma unroll
        for (int i = 0; i < 2; i++) {
            int idx = tid + i * 256;
            int row = idx >> 4;
            int c8  = idx & 15;
            float4 v = *(const float4*)&x[(size_t)(bm + row) * HID + kc + c8 * 4];
            *(uint2*)&As[row][c8 * 2] = make_uint2(pack_h2(v.x, v.y), pack_h2(v.z, v.w));
        }
        #pragma unroll
        for (int i = 0; i < 4; i++) {
            int idx = tid + i * 256;
            int row = idx >> 4;           // dot index 0..63
            int c8  = idx & 15;
            int qk   = row >> 5;
            int dd   = row & 31;
            int h    = dd >> 1;
            int slot = (dd & 1) * 2;
            const float* Wr = (qk ? Wk : Wq) + (size_t)(h * HDD + slot) * HID;
            float4 v = *(const float4*)&Wr[kc + c8 * 4];
            *(uint2*)&Ws[row][c8 * 2] = make_uint2(pack_h2(v.x, v.y), pack_h2(v.z, v.w));
        }
        __syncthreads();

        #pragma unroll
        for (int ks2 = 0; ks2 < 32; ks2 += 8) {
            uint32_t af[4];
            int r0 = wm + gid;
            af[0] = As[r0][ks2 + tig];
            af[1] = As[r0 + 8][ks2 + tig];
            af[2] = As[r0][ks2 + tig + 4];
            af[3] = As[r0 + 8][ks2 + tig + 4];
            #pragma unroll
            for (int nt = 0; nt < 2; nt++) {
                int n0 = wn + nt * 8 + gid;
                uint32_t bf[2];
                bf[0] = Ws[n0][ks2 + tig];
                bf[1] = Ws[n0][ks2 + tig + 4];
                mma_f16_k16(c[nt], af, bf);
            }
        }
    }

    #pragma unroll
    for (int nt = 0; nt < 2; nt++) {
        int col0 = wn + nt * 8 + 2 * tig;
        int qk = col0 >> 5;
        int dd = col0 & 31;
        int h  = dd >> 1;
        const float* bb = qk ? bk : bq;
        float b0 = bb[h * HDD + 0];
        float b1 = bb[h * HDD + 2];
        float sc0 = (qk == 0) ? 0.125f : 1.0f;
        float sc1 = (qk == 0) ? 0.1f   : 1.0f;
        #pragma unroll
        for (int hf = 0; hf < 2; hf++) {
            int m = bm + wm + gid + hf * 8;
            float t0 = c[nt][hf * 2 + 0] + b0;
            float t1 = c[nt][hf * 2 + 1] + b1;

            float a0 = 1.0f / (1.0f + expf(-t0));
            float na0 = 1.0f - a0;
            float nei0 = fminf(fmaxf(1.0f - (a0 + na0), 0.0f), 1.0f);
            float a1 = 1.0f / (1.0f + expf(-t1));
            float na1 = 1.0f - a1;
            float nei1 = fminf(fmaxf(1.0f - (a1 + na1), 0.0f), 1.0f);

            uint4 out;
            out.x = pack_h2(a0 * sc0, na0 * sc0);
            out.y = pack_h2(a0 * na0 * sc0, nei0 * sc0);
            out.z = pack_h2(a1 * sc1, na1 * sc1);
            out.w = pack_h2(a1 * na1 * sc1, nei1 * sc1);

            int b_ = m / SEQ;
            int s_ = m % SEQ;
            uint32_t* dst = (qk ? g_Kch : g_Qch) + ((size_t)(b_ * NHD + h) * SEQ + s_) * 4;
            *(uint4*)dst = out;
        }
    }
}

// ---------------------------------------------------------------------------
// Kernel 2/4: fp16 mma GEMM (m16n8k16) — REVERTED to round-11 single-buffer
// version (verified 48.6 us; the R13 double-buffer regressed to 61 us via
// occupancy collapse).
// ---------------------------------------------------------------------------
__global__ __launch_bounds__(256) void gemm_mma_kernel(
    const float* __restrict__ Ain, const float* __restrict__ W,
    const float* __restrict__ bias, float* __restrict__ Cout, int mode)
{
    __shared__ uint32_t As[128][20];
    __shared__ uint32_t Bs[128][20];

    const int tid  = threadIdx.x;
    const int lane = tid & 31;
    const int wid  = tid >> 5;
    const int bm   = blockIdx.y * 128;
    const int bn   = blockIdx.x * 128;
    const int wm   = (wid & 1) * 64;
    const int wn   = (wid >> 1) * 32;
    const int gid  = lane >> 2;
    const int tig  = lane & 3;

    float c[4][4][4];
    #pragma unroll
    for (int mt = 0; mt < 4; mt++)
        #pragma unroll
        for (int nt = 0; nt < 4; nt++)
            #pragma unroll
            for (int k = 0; k < 4; k++) c[mt][nt][k] = 0.0f;

    for (int kc = 0; kc < HID; kc += 32) {
        __syncthreads();
        #pragma unroll
        for (int i = 0; i < 4; i++) {
            int idx  = tid + i * 256;
            int row  = idx >> 3;
            int c8   = (idx & 7);
            float4 vb = *(const float4*)&W[(size_t)(bn + row) * HID + kc + c8 * 4];
            Bs[row][c8 * 2]     = pack_h2(vb.x, vb.y);
            Bs[row][c8 * 2 + 1] = pack_h2(vb.z, vb.w);
            if (mode == 0) {
                float4 va = *(const float4*)&Ain[(size_t)(bm + row) * HID + kc + c8 * 4];
                As[row][c8 * 2]     = pack_h2(va.x, va.y);
                As[row][c8 * 2 + 1] = pack_h2(va.z, va.w);
            } else {
                uint2 va = *(const uint2*)&g_AttOut[(size_t)(bm + row) * HID + kc + c8 * 4];
                As[row][c8 * 2]     = va.x;
                As[row][c8 * 2 + 1] = va.y;
            }
        }
        __syncthreads();

        #pragma unroll
        for (int ks2 = 0; ks2 < 16; ks2 += 8) {
            uint32_t af[4][4];
            #pragma unroll
            for (int mt = 0; mt < 4; mt++) {
                int r0 = wm + mt * 16 + gid;
                af[mt][0] = As[r0][ks2 + tig];
                af[mt][1] = As[r0 + 8][ks2 + tig];
                af[mt][2] = As[r0][ks2 + tig + 4];
                af[mt][3] = As[r0 + 8][ks2 + tig + 4];
            }
            uint32_t bf[4][2];
            #pragma unroll
            for (int nt = 0; nt < 4; nt++) {
                int n0 = wn + nt * 8 + gid;
                bf[nt][0] = Bs[n0][ks2 + tig];
                bf[nt][1] = Bs[n0][ks2 + tig + 4];
            }
            #pragma unroll
            for (int mt = 0; mt < 4; mt++)
                #pragma unroll
                for (int nt = 0; nt < 4; nt++)
                    mma_f16_k16(c[mt][nt], af[mt], bf[nt]);
        }
    }

    if (mode == 0) {
        // pack row-pairs (2p, 2p+1) into half2 for attention's V B-fragments
        #pragma unroll
        for (int mt = 0; mt < 4; mt++) {
            int rbase = bm + wm + mt * 16 + (gid & ~1);
            int p0 = rbase >> 1;
            #pragma unroll
            for (int nt = 0; nt < 4; nt++) {
                int col0 = bn + wn + nt * 8 + 2 * tig;
                float b0 = bias[col0], b1 = bias[col0 + 1];
                float v0 = c[mt][nt][0] + b0;
                float v1 = c[mt][nt][1] + b1;
                float v2 = c[mt][nt][2] + b0;
                float v3 = c[mt][nt][3] + b1;
                float o0 = __shfl_xor_sync(0xffffffffu, v0, 4);
                float o1 = __shfl_xor_sync(0xffffffffu, v1, 4);
                float o2 = __shfl_xor_sync(0xffffffffu, v2, 4);
                float o3 = __shfl_xor_sync(0xffffffffu, v3, 4);
                if ((gid & 1) == 0) {
                    g_Vp[(size_t)p0 * HID + col0]       = pack_h2(v0, o0);
                    g_Vp[(size_t)(p0 + 4) * HID + col0] = pack_h2(v2, o2);
                } else {
                    g_Vp[(size_t)p0 * HID + col0 + 1]       = pack_h2(o1, v1);
                    g_Vp[(size_t)(p0 + 4) * HID + col0 + 1] = pack_h2(o3, v3);
                }
            }
        }
    } else {
        #pragma unroll
        for (int mt = 0; mt < 4; mt++) {
            int row0 = bm + wm + mt * 16 + gid;
            #pragma unroll
            for (int nt = 0; nt < 4; nt++) {
                int col0 = bn + wn + nt * 8 + 2 * tig;
                float b0 = bias[col0], b1 = bias[col0 + 1];
                float2 v0; v0.x = c[mt][nt][0] + b0; v0.y = c[mt][nt][1] + b1;
                float2 v1; v1.x = c[mt][nt][2] + b0; v1.y = c[mt][nt][3] + b1;
                *(float2*)&Cout[(size_t)row0 * HID + col0] = v0;
                *(float2*)&Cout[(size_t)(row0 + 8) * HID + col0] = v1;
            }
        }
    }
}

// ---------------------------------------------------------------------------
// Kernel 3: fp16 attention, register-resident P (no Ps smem, no mid sync).
// BQ=128: warp w owns q-rows [16w, 16w+16). Per 64-key tile:
//   S: 8 n-tiles of m16n8k8 (K=8 = full rank)
//   exp in regs; S-accumulator fragment == O A-fragment after half2 packing
//   O: 4 k16-steps x 8 n-tiles of m16n8k16, V pre-packed row-pair layout.
// Z per-thread, butterfly-reduced at the end (no smem, no atomics).
// ---------------------------------------------------------------------------
#define BQ 128
#define BK 64

__global__ __launch_bounds__(256) void attn_mma_kernel()
{
    __shared__ uint32_t Qs[BQ][4];      // [token][4 half2]
    __shared__ uint32_t Ks[BK][4];
    __shared__ uint32_t Vs[BK / 2][72]; // [token-pair][64 dims + pad]

    const int tid  = threadIdx.x;
    const int lane = tid & 31;
    const int wid  = tid >> 5;
    const int gid  = lane >> 2;
    const int tig  = lane & 3;
    const int q0   = blockIdx.x * BQ;
    const int h    = blockIdx.y;
    const int b    = blockIdx.z;

    const uint32_t* Qg = g_Qch + ((size_t)(b * NHD + h) * SEQ + q0) * 4;
    const uint32_t* Kg = g_Kch + ((size_t)(b * NHD + h) * SEQ) * 4;
    const uint32_t* Vg = g_Vp + (size_t)b * (SEQ / 2) * HID + h * HDD;

    // stage Q tile (128 tokens x 4 half2 = 512 u32)
    ((uint32_t*)Qs)[tid]       = Qg[tid];
    ((uint32_t*)Qs)[tid + 256] = Qg[tid + 256];
    __syncthreads();

    // Q A-fragment (m16n8k8: 2 regs), rows 16*wid + {gid, gid+8}
    uint32_t aq[2];
    aq[0] = Qs[wid * 16 + gid][tig];
    aq[1] = Qs[wid * 16 + gid + 8][tig];

    float o[8][4];
    #pragma unroll
    for (int nt = 0; nt < 8; nt++)
        #pragma unroll
        for (int k = 0; k < 4; k++) o[nt][k] = 0.0f;
    float zacc0 = 0.0f, zacc1 = 0.0f;

    for (int kt = 0; kt < SEQ; kt += BK) {
        __syncthreads();   // prev O-phase done with Ks/Vs
        ((uint32_t*)Ks)[tid] = Kg[kt * 4 + tid];
        #pragma unroll
        for (int i = 0; i < 8; i++) {
            int idx = tid + i * 256;
            int t2  = idx >> 6;
            int d   = idx & 63;
            Vs[t2][d] = Vg[(size_t)(kt / 2 + t2) * HID + d];
        }
        __syncthreads();

        // ---- S phase: rows 16w..16w+15 x all 64 keys = 8 n-tiles ----
        float e[8][4];
        #pragma unroll
        for (int j = 0; j < 8; j++) {
            uint32_t bk_ = Ks[j * 8 + gid][tig];
            float c[4] = {0.f, 0.f, 0.f, 0.f};
            mma_f16_k8(c, aq, &bk_);
            e[j][0] = exp_pos(c[0]);
            e[j][1] = exp_pos(c[1]);
            e[j][2] = exp_pos(c[2]);
            e[j][3] = exp_pos(c[3]);
            zacc0 += e[j][0] + e[j][1];
            zacc1 += e[j][2] + e[j][3];
        }

        // ---- O phase: P(16x64) @ V(64x64); A-fragments from registers ----
        #pragma unroll
        for (int kk = 0; kk < 4; kk++) {
            uint32_t ap[4];
            ap[0] = pack_h2(e[2 * kk][0],     e[2 * kk][1]);      // row gid,   k 16kk+2tig
            ap[1] = pack_h2(e[2 * kk][2],     e[2 * kk][3]);      // row gid+8
            ap[2] = pack_h2(e[2 * kk + 1][0], e[2 * kk + 1][1]);  // row gid,   k 16kk+8+2tig
            ap[3] = pack_h2(e[2 * kk + 1][2], e[2 * kk + 1][3]);  // row gid+8
            const int k2 = kk * 8;
            #pragma unroll
            for (int nt = 0; nt < 8; nt++) {
                int n0 = nt * 8 + gid;
                uint32_t bv[2];
                bv[0] = Vs[k2 + tig][n0];
                bv[1] = Vs[k2 + tig + 4][n0];
                mma_f16_k16(o[nt], ap, bv);
            }
        }
    }

    // ---- Z reduction: butterfly over the 4-lane tig group ----
    zacc0 += __shfl_xor_sync(0xffffffffu, zacc0, 1);
    zacc0 += __shfl_xor_sync(0xffffffffu, zacc0, 2);
    zacc1 += __shfl_xor_sync(0xffffffffu, zacc1, 1);
    zacc1 += __shfl_xor_sync(0xffffffffu, zacc1, 2);
    const float inv0 = 1.0f / zacc0;
    const float inv1 = 1.0f / zacc1;

    // ---- normalize + store (half, row-major for GEMM-1) ----
    uint32_t* Og = (uint32_t*)g_AttOut;   // half2 view, HID/2 per row
    const size_t r0 = (size_t)(b * SEQ + q0 + wid * 16 + gid);
    const int cbase = (h * HDD) >> 1;
    #pragma unroll
    for (int nt = 0; nt < 8; nt++) {
        int cc2 = cbase + nt * 4 + tig;
        Og[r0 * (HID / 2) + cc2]       = pack_h2(o[nt][0] * inv0, o[nt][1] * inv0);
        Og[(r0 + 8) * (HID / 2) + cc2] = pack_h2(o[nt][2] * inv1, o[nt][3] * inv1);
    }
}

// ---------------------------------------------------------------------------
extern "C" void kernel_launch(void* const* d_in, const int* in_sizes, int n_in,
                              void* d_out, int out_size)
{
    const float* x = nullptr;
    const float* Wm[4] = {nullptr, nullptr, nullptr, nullptr};
    const float* bm[4] = {nullptr, nullptr, nullptr, nullptr};
    int wi = 0, bi = 0;
    for (int i = 0; i < n_in; i++) {
        if (in_sizes[i] == NB * SEQ * HID)      x = (const float*)d_in[i];
        else if (in_sizes[i] == HID * HID) { if (wi < 4) Wm[wi++] = (const float*)d_in[i]; }
        else if (in_sizes[i] == HID)       { if (bi < 4) bm[bi++] = (const float*)d_in[i]; }
    }
    const float* Wq = Wm[0]; const float* Wk = Wm[1];
    const float* Wv = Wm[2]; const float* Wo = Wm[3];
    const float* bq = bm[0]; const float* bk = bm[1];
    const float* bv = bm[2]; const float* bo = bm[3];
    float* out = (float*)d_out;

    const int M = NB * SEQ;  // 4096

    qk_mma_kernel<<<M / QK_BM, 256>>>(x, Wq, Wk, bq, bk);
    {
        dim3 grid(HID / 128, M / 128);
        gemm_mma_kernel<<<grid, 256>>>(x, Wv, bv, nullptr, 0);
    }
    {
        dim3 grid(SEQ / BQ, NHD, NB);
        attn_mma_kernel<<<grid, 256>>>();
    }
    {
        dim3 grid(HID / 128, M / 128);
        gemm_mma_kernel<<<grid, 256>>>(nullptr, Wo, bo, out, 1);
    }
}

// round 15
// speedup vs baseline: 3.5572x; 1.0800x over previous
#include <cuda_runtime.h>
#include <cuda_fp16.h>
#include <cstdint>

#define NB   2
#define SEQ  2048
#define HID  1024
#define NHD  16
#define HDD  64

// Scratch (allocation-free rule). Referenced ONLY from device code.
__device__ uint32_t g_Qch[NB * NHD * SEQ * 4];  // [token][4 half2] (8 channels)
__device__ uint32_t g_Kch[NB * NHD * SEQ * 4];
__device__ uint32_t g_Vp[(NB * SEQ / 2) * HID]; // row-PAIR packed half2
__device__ __half   g_AttOut[NB * SEQ * HID];   // plain row-major half
__device__ __half   g_Xh[NB * SEQ * HID];       // x pre-rounded to half
__device__ __half   g_Wvh[HID * HID];           // Wv pre-rounded to half
__device__ __half   g_Woh[HID * HID];           // Wo pre-rounded to half

// ---------------------------------------------------------------------------
// helpers
// ---------------------------------------------------------------------------
__device__ __forceinline__ uint32_t pack_h2(float lo, float hi) {
    __half2 h = __floats2half2_rn(lo, hi);
    return *(uint32_t*)&h;
}
__device__ __forceinline__ void mma_f16_k16(float* d, const uint32_t* a, const uint32_t* b) {
    asm volatile(
        "mma.sync.aligned.m16n8k16.row.col.f32.f16.f16.f32 "
        "{%0,%1,%2,%3}, {%4,%5,%6,%7}, {%8,%9}, {%0,%1,%2,%3};"
        : "+f"(d[0]), "+f"(d[1]), "+f"(d[2]), "+f"(d[3])
        : "r"(a[0]), "r"(a[1]), "r"(a[2]), "r"(a[3]), "r"(b[0]), "r"(b[1]));
}
__device__ __forceinline__ void mma_f16_k8(float* d, const uint32_t* a, const uint32_t* b) {
    asm volatile(
        "mma.sync.aligned.m16n8k8.row.col.f32.f16.f16.f32 "
        "{%0,%1,%2,%3}, {%4,%5}, {%6}, {%0,%1,%2,%3};"
        : "+f"(d[0]), "+f"(d[1]), "+f"(d[2]), "+f"(d[3])
        : "r"(a[0]), "r"(a[1]), "r"(b[0]));
}
// exp(x), x in [0, ~0.5]: degree-5 Taylor, rel err < 1.5e-5
__device__ __forceinline__ float exp_pos(float x) {
    return 1.0f + x * (1.0f + x * (0.5f + x * (0.16666667f
           + x * (0.041666667f + x * 0.0083333333f))));
}
__device__ __forceinline__ uint32_t smem_u32(const void* p) {
    uint32_t a;
    asm("{ .reg .u64 t; cvta.to.shared.u64 t, %1; cvt.u32.u64 %0, t; }" : "=r"(a) : "l"(p));
    return a;
}
__device__ __forceinline__ void cp16(uint32_t dst, const void* src) {
    asm volatile("cp.async.ca.shared.global [%0], [%1], 16;" :: "r"(dst), "l"(src));
}
#define CP_COMMIT() asm volatile("cp.async.commit_group;" ::: "memory")
#define CP_WAIT(n)  asm volatile("cp.async.wait_group %0;" :: "n"(n) : "memory")

// ---------------------------------------------------------------------------
// Kernel 0: pre-round x, Wv, Wo to half (numerically identical to the cvt
// previously done at GEMM staging; enables raw cp.async staging).
// ---------------------------------------------------------------------------
__global__ __launch_bounds__(256) void prep_half_kernel(
    const float* __restrict__ x, const float* __restrict__ Wv, const float* __restrict__ Wo)
{
    const int n1 = NB * SEQ * HID / 4;
    const int n2 = HID * HID / 4;
    const int total = n1 + 2 * n2;
    for (int i = blockIdx.x * 256 + threadIdx.x; i < total; i += gridDim.x * 256) {
        const float4* src;
        uint2* dst;
        if (i < n1)           { src = (const float4*)x  + i;             dst = (uint2*)g_Xh  + i; }
        else if (i < n1 + n2) { src = (const float4*)Wv + (i - n1);      dst = (uint2*)g_Wvh + (i - n1); }
        else                  { src = (const float4*)Wo + (i - n1 - n2); dst = (uint2*)g_Woh + (i - n1 - n2); }
        float4 v = *src;
        *dst = make_uint2(pack_h2(v.x, v.y), pack_h2(v.z, v.w));
    }
}

// ---------------------------------------------------------------------------
// Kernel 1: QK projection as fp16 mma GEMM + tetra-channel epilogue.
// (verified ~12 us in round 13; unchanged)
// ---------------------------------------------------------------------------
#define QK_BM 32

__global__ __launch_bounds__(256) void qk_mma_kernel(
    const float* __restrict__ x,
    const float* __restrict__ Wq, const float* __restrict__ Wk,
    const float* __restrict__ bq, const float* __restrict__ bk)
{
    __shared__ uint32_t As[QK_BM][36];
    __shared__ uint32_t Ws[64][36];

    const int tid  = threadIdx.x;
    const int lane = tid & 31;
    const int wid  = tid >> 5;
    const int gid  = lane >> 2;
    const int tig  = lane & 3;
    const int bm   = blockIdx.x * QK_BM;
    const int wm   = (wid & 1) * 16;
    const int wn   = (wid >> 1) * 16;

    float c[2][4];
    #pragma unroll
    for (int nt = 0; nt < 2; nt++)
        #pragma unroll
        for (int k = 0; k < 4; k++) c[nt][k] = 0.0f;

    for (int kc = 0; kc < HID; kc += 64) {
        __syncthreads();
        #pragma unroll
        for (int i = 0; i < 2; i++) {
            int idx = tid + i * 256;
            int row = idx >> 4;
            int c8  = idx & 15;
            float4 v = *(const float4*)&x[(size_t)(bm + row) * HID + kc + c8 * 4];
            *(uint2*)&As[row][c8 * 2] = make_uint2(pack_h2(v.x, v.y), pack_h2(v.z, v.w));
        }
        #pragma unroll
        for (int i = 0; i < 4; i++) {
            int idx = tid + i * 256;
            int row = idx >> 4;           // dot index 0..63
            int c8  = idx & 15;
            int qk   = row >> 5;
            int dd   = row & 31;
            int h    = dd >> 1;
            int slot = (dd & 1) * 2;
            const float* Wr = (qk ? Wk : Wq) + (size_t)(h * HDD + slot) * HID;
            float4 v = *(const float4*)&Wr[kc + c8 * 4];
            *(uint2*)&Ws[row][c8 * 2] = make_uint2(pack_h2(v.x, v.y), pack_h2(v.z, v.w));
        }
        __syncthreads();

        #pragma unroll
        for (int ks2 = 0; ks2 < 32; ks2 += 8) {
            uint32_t af[4];
            int r0 = wm + gid;
            af[0] = As[r0][ks2 + tig];
            af[1] = As[r0 + 8][ks2 + tig];
            af[2] = As[r0][ks2 + tig + 4];
            af[3] = As[r0 + 8][ks2 + tig + 4];
            #pragma unroll
            for (int nt = 0; nt < 2; nt++) {
                int n0 = wn + nt * 8 + gid;
                uint32_t bf[2];
                bf[0] = Ws[n0][ks2 + tig];
                bf[1] = Ws[n0][ks2 + tig + 4];
                mma_f16_k16(c[nt], af, bf);
            }
        }
    }

    #pragma unroll
    for (int nt = 0; nt < 2; nt++) {
        int col0 = wn + nt * 8 + 2 * tig;
        int qk = col0 >> 5;
        int dd = col0 & 31;
        int h  = dd >> 1;
        const float* bb = qk ? bk : bq;
        float b0 = bb[h * HDD + 0];
        float b1 = bb[h * HDD + 2];
        float sc0 = (qk == 0) ? 0.125f : 1.0f;
        float sc1 = (qk == 0) ? 0.1f   : 1.0f;
        #pragma unroll
        for (int hf = 0; hf < 2; hf++) {
            int m = bm + wm + gid + hf * 8;
            float t0 = c[nt][hf * 2 + 0] + b0;
            float t1 = c[nt][hf * 2 + 1] + b1;

            float a0 = 1.0f / (1.0f + expf(-t0));
            float na0 = 1.0f - a0;
            float nei0 = fminf(fmaxf(1.0f - (a0 + na0), 0.0f), 1.0f);
            float a1 = 1.0f / (1.0f + expf(-t1));
            float na1 = 1.0f - a1;
            float nei1 = fminf(fmaxf(1.0f - (a1 + na1), 0.0f), 1.0f);

            uint4 out;
            out.x = pack_h2(a0 * sc0, na0 * sc0);
            out.y = pack_h2(a0 * na0 * sc0, nei0 * sc0);
            out.z = pack_h2(a1 * sc1, na1 * sc1);
            out.w = pack_h2(a1 * na1 * sc1, nei1 * sc1);

            int b_ = m / SEQ;
            int s_ = m % SEQ;
            uint32_t* dst = (qk ? g_Kch : g_Qch) + ((size_t)(b_ * NHD + h) * SEQ + s_) * 4;
            *(uint4*)dst = out;
        }
    }
}

// ---------------------------------------------------------------------------
// Kernel 2/4: fp16 mma GEMM, cp.async double-buffered (no staging registers,
// no cvt in loop — all inputs pre-halved).
// mode 0: A = g_Xh,    W = g_Wvh, C -> g_Vp row-pair half2.
// mode 1: A = g_AttOut, W = g_Woh, C -> Cout fp32.
// ---------------------------------------------------------------------------
__global__ __launch_bounds__(256) void gemm_mma_kernel(
    const float* __restrict__ bias, float* __restrict__ Cout, int mode)
{
    __shared__ __align__(16) uint32_t As[2][128][20];
    __shared__ __align__(16) uint32_t Bs[2][128][20];

    const __half* A = (mode == 0) ? g_Xh  : g_AttOut;
    const __half* W = (mode == 0) ? g_Wvh : g_Woh;

    const int tid  = threadIdx.x;
    const int lane = tid & 31;
    const int wid  = tid >> 5;
    const int bm   = blockIdx.y * 128;
    const int bn   = blockIdx.x * 128;
    const int wm   = (wid & 1) * 64;
    const int wn   = (wid >> 1) * 32;
    const int gid  = lane >> 2;
    const int tig  = lane & 3;

    const uint32_t sA = smem_u32(As);
    const uint32_t sB = smem_u32(Bs);
    // staging: idx in [0,512): row = idx>>2, q = idx&3 (16B chunk)
    const int srow = tid >> 1;                 // with i-loop below covers 0..127 x 4 chunks
    // each thread does 2 chunks per matrix: (tid, tid+256)

    float c[4][4][4];
    #pragma unroll
    for (int mt = 0; mt < 4; mt++)
        #pragma unroll
        for (int nt = 0; nt < 4; nt++)
            #pragma unroll
            for (int k = 0; k < 4; k++) c[mt][nt][k] = 0.0f;

    // prologue: stage chunk 0 into buffer 0
    #pragma unroll
    for (int i = 0; i < 2; i++) {
        int idx = tid + i * 256;
        int row = idx >> 2;
        int q   = idx & 3;
        cp16(sA + (uint32_t)(row * 80 + q * 16), A + (size_t)(bm + row) * HID + q * 8);
        cp16(sB + (uint32_t)(row * 80 + q * 16), W + (size_t)(bn + row) * HID + q * 8);
    }
    CP_COMMIT();

    const int NCH = HID / 32;   // 32 chunks
    for (int ch = 0; ch < NCH; ch++) {
        const int buf = ch & 1;
        const bool more = (ch + 1 < NCH);
        if (more) {
            const int nb = buf ^ 1;
            const int kc = (ch + 1) * 32;
            #pragma unroll
            for (int i = 0; i < 2; i++) {
                int idx = tid + i * 256;
                int row = idx >> 2;
                int q   = idx & 3;
                cp16(sA + (uint32_t)(nb * 10240 + row * 80 + q * 16),
                     A + (size_t)(bm + row) * HID + kc + q * 8);
                cp16(sB + (uint32_t)(nb * 10240 + row * 80 + q * 16),
                     W + (size_t)(bn + row) * HID + kc + q * 8);
            }
            CP_COMMIT();
            CP_WAIT(1);
        } else {
            CP_WAIT(0);
        }
        __syncthreads();

        #pragma unroll
        for (int ks2 = 0; ks2 < 16; ks2 += 8) {
            uint32_t af[4][4];
            #pragma unroll
            for (int mt = 0; mt < 4; mt++) {
                int r0 = wm + mt * 16 + gid;
                af[mt][0] = As[buf][r0][ks2 + tig];
                af[mt][1] = As[buf][r0 + 8][ks2 + tig];
                af[mt][2] = As[buf][r0][ks2 + tig + 4];
                af[mt][3] = As[buf][r0 + 8][ks2 + tig + 4];
            }
            uint32_t bf[4][2];
            #pragma unroll
            for (int nt = 0; nt < 4; nt++) {
                int n0 = wn + nt * 8 + gid;
                bf[nt][0] = Bs[buf][n0][ks2 + tig];
                bf[nt][1] = Bs[buf][n0][ks2 + tig + 4];
            }
            #pragma unroll
            for (int mt = 0; mt < 4; mt++)
                #pragma unroll
                for (int nt = 0; nt < 4; nt++)
                    mma_f16_k16(c[mt][nt], af[mt], bf[nt]);
        }
        __syncthreads();   // compute done before this buf is restaged next iter
    }

    if (mode == 0) {
        // pack row-pairs (2p, 2p+1) into half2 for attention's V B-fragments
        #pragma unroll
        for (int mt = 0; mt < 4; mt++) {
            int rbase = bm + wm + mt * 16 + (gid & ~1);
            int p0 = rbase >> 1;
            #pragma unroll
            for (int nt = 0; nt < 4; nt++) {
                int col0 = bn + wn + nt * 8 + 2 * tig;
                float b0 = bias[col0], b1 = bias[col0 + 1];
                float v0 = c[mt][nt][0] + b0;
                float v1 = c[mt][nt][1] + b1;
                float v2 = c[mt][nt][2] + b0;
                float v3 = c[mt][nt][3] + b1;
                float o0 = __shfl_xor_sync(0xffffffffu, v0, 4);
                float o1 = __shfl_xor_sync(0xffffffffu, v1, 4);
                float o2 = __shfl_xor_sync(0xffffffffu, v2, 4);
                float o3 = __shfl_xor_sync(0xffffffffu, v3, 4);
                if ((gid & 1) == 0) {
                    g_Vp[(size_t)p0 * HID + col0]       = pack_h2(v0, o0);
                    g_Vp[(size_t)(p0 + 4) * HID + col0] = pack_h2(v2, o2);
                } else {
                    g_Vp[(size_t)p0 * HID + col0 + 1]       = pack_h2(o1, v1);
                    g_Vp[(size_t)(p0 + 4) * HID + col0 + 1] = pack_h2(o3, v3);
                }
            }
        }
    } else {
        #pragma unroll
        for (int mt = 0; mt < 4; mt++) {
            int row0 = bm + wm + mt * 16 + gid;
            #pragma unroll
            for (int nt = 0; nt < 4; nt++) {
                int col0 = bn + wn + nt * 8 + 2 * tig;
                float b0 = bias[col0], b1 = bias[col0 + 1];
                float2 v0; v0.x = c[mt][nt][0] + b0; v0.y = c[mt][nt][1] + b1;
                float2 v1; v1.x = c[mt][nt][2] + b0; v1.y = c[mt][nt][3] + b1;
                *(float2*)&Cout[(size_t)row0 * HID + col0] = v0;
                *(float2*)&Cout[(size_t)(row0 + 8) * HID + col0] = v1;
            }
        }
    }
}

// ---------------------------------------------------------------------------
// Kernel 3: fp16 attention, register-resident P + cp.async double-buffered
// K/V tiles (BQ=128, BK=64; structure otherwise as verified in round 14).
// ---------------------------------------------------------------------------
#define BQ 128
#define BK 64

__global__ __launch_bounds__(256) void attn_mma_kernel()
{
    __shared__ __align__(16) uint32_t Qs[BQ][4];
    __shared__ __align__(16) uint32_t Ks[2][BK][4];
    __shared__ __align__(16) uint32_t Vs[2][BK / 2][72];

    const int tid  = threadIdx.x;
    const int lane = tid & 31;
    const int wid  = tid >> 5;
    const int gid  = lane >> 2;
    const int tig  = lane & 3;
    const int q0   = blockIdx.x * BQ;
    const int h    = blockIdx.y;
    const int b    = blockIdx.z;

    const uint32_t* Qg = g_Qch + ((size_t)(b * NHD + h) * SEQ + q0) * 4;
    const uint32_t* Kg = g_Kch + ((size_t)(b * NHD + h) * SEQ) * 4;
    const uint32_t* Vg = g_Vp + (size_t)b * (SEQ / 2) * HID + h * HDD;

    const uint32_t sK = smem_u32(Ks);
    const uint32_t sV = smem_u32(Vs);

    // stage Q tile (128 tokens x 4 half2 = 512 u32)
    ((uint32_t*)Qs)[tid]       = Qg[tid];
    ((uint32_t*)Qs)[tid + 256] = Qg[tid + 256];

    // prologue: stage tile 0 into buffer 0
    #pragma unroll
    for (int i = 0; i < 2; i++) {
        int idx = tid + i * 256;          // V chunk id 0..511 (each 4 u32)
        int t2  = idx >> 4;               // pair row 0..31
        int q   = idx & 15;               // 16 chunks of 4 u32 per row
        cp16(sV + (uint32_t)(t2 * 288 + q * 16), Vg + (size_t)t2 * HID + q * 4);
    }
    if (tid < BK)
        cp16(sK + (uint32_t)(tid * 16), Kg + (size_t)tid * 4);
    CP_COMMIT();
    __syncthreads();

    // Q A-fragment (m16n8k8: 2 regs), rows 16*wid + {gid, gid+8}
    uint32_t aq[2];
    aq[0] = Qs[wid * 16 + gid][tig];
    aq[1] = Qs[wid * 16 + gid + 8][tig];

    float o[8][4];
    #pragma unroll
    for (int nt = 0; nt < 8; nt++)
        #pragma unroll
        for (int k = 0; k < 4; k++) o[nt][k] = 0.0f;
    float zacc0 = 0.0f, zacc1 = 0.0f;

    const int NT = SEQ / BK;   // 32 tiles
    for (int it = 0; it < NT; it++) {
        const int buf = it & 1;
        const bool more = (it + 1 < NT);
        if (more) {
            const int nb = buf ^ 1;
            const int kt = (it + 1) * BK;
            #pragma unroll
            for (int i = 0; i < 2; i++) {
                int idx = tid + i * 256;
                int t2  = idx >> 4;
                int q   = idx & 15;
                cp16(sV + (uint32_t)(nb * 9216 + t2 * 288 + q * 16),
                     Vg + (size_t)(kt / 2 + t2) * HID + q * 4);
            }
            if (tid < BK)
                cp16(sK + (uint32_t)(nb * 1024 + tid * 16), Kg + (size_t)(kt + tid) * 4);
            CP_COMMIT();
            CP_WAIT(1);
        } else {
            CP_WAIT(0);
        }
        __syncthreads();

        // ---- S phase: rows 16w..16w+15 x all 64 keys = 8 n-tiles ----
        float e[8][4];
        #pragma unroll
        for (int j = 0; j < 8; j++) {
            uint32_t bk_ = Ks[buf][j * 8 + gid][tig];
            float c[4] = {0.f, 0.f, 0.f, 0.f};
            mma_f16_k8(c, aq, &bk_);
            e[j][0] = exp_pos(c[0]);
            e[j][1] = exp_pos(c[1]);
            e[j][2] = exp_pos(c[2]);
            e[j][3] = exp_pos(c[3]);
            zacc0 += e[j][0] + e[j][1];
            zacc1 += e[j][2] + e[j][3];
        }

        // ---- O phase: P(16x64) @ V(64x64); A-fragments from registers ----
        #pragma unroll
        for (int kk = 0; kk < 4; kk++) {
            uint32_t ap[4];
            ap[0] = pack_h2(e[2 * kk][0],     e[2 * kk][1]);
            ap[1] = pack_h2(e[2 * kk][2],     e[2 * kk][3]);
            ap[2] = pack_h2(e[2 * kk + 1][0], e[2 * kk + 1][1]);
            ap[3] = pack_h2(e[2 * kk + 1][2], e[2 * kk + 1][3]);
            const int k2 = kk * 8;
            #pragma unroll
            for (int nt = 0; nt < 8; nt++) {
                int n0 = nt * 8 + gid;
                uint32_t bv[2];
                bv[0] = Vs[buf][k2 + tig][n0];
                bv[1] = Vs[buf][k2 + tig + 4][n0];
                mma_f16_k16(o[nt], ap, bv);
            }
        }
        __syncthreads();   // compute done before this buf is restaged next iter
    }

    // ---- Z reduction: butterfly over the 4-lane tig group ----
    zacc0 += __shfl_xor_sync(0xffffffffu, zacc0, 1);
    zacc0 += __shfl_xor_sync(0xffffffffu, zacc0, 2);
    zacc1 += __shfl_xor_sync(0xffffffffu, zacc1, 1);
    zacc1 += __shfl_xor_sync(0xffffffffu, zacc1, 2);
    const float inv0 = 1.0f / zacc0;
    const float inv1 = 1.0f / zacc1;

    // ---- normalize + store (half, row-major for GEMM-1) ----
    uint32_t* Og = (uint32_t*)g_AttOut;   // half2 view, HID/2 per row
    const size_t r0 = (size_t)(b * SEQ + q0 + wid * 16 + gid);
    const int cbase = (h * HDD) >> 1;
    #pragma unroll
    for (int nt = 0; nt < 8; nt++) {
        int cc2 = cbase + nt * 4 + tig;
        Og[r0 * (HID / 2) + cc2]       = pack_h2(o[nt][0] * inv0, o[nt][1] * inv0);
        Og[(r0 + 8) * (HID / 2) + cc2] = pack_h2(o[nt][2] * inv1, o[nt][3] * inv1);
    }
}

// ---------------------------------------------------------------------------
extern "C" void kernel_launch(void* const* d_in, const int* in_sizes, int n_in,
                              void* d_out, int out_size)
{
    const float* x = nullptr;
    const float* Wm[4] = {nullptr, nullptr, nullptr, nullptr};
    const float* bm[4] = {nullptr, nullptr, nullptr, nullptr};
    int wi = 0, bi = 0;
    for (int i = 0; i < n_in; i++) {
        if (in_sizes[i] == NB * SEQ * HID)      x = (const float*)d_in[i];
        else if (in_sizes[i] == HID * HID) { if (wi < 4) Wm[wi++] = (const float*)d_in[i]; }
        else if (in_sizes[i] == HID)       { if (bi < 4) bm[bi++] = (const float*)d_in[i]; }
    }
    const float* Wq = Wm[0]; const float* Wk = Wm[1];
    const float* Wv = Wm[2]; const float* Wo = Wm[3];
    const float* bq = bm[0]; const float* bk = bm[1];
    const float* bv = bm[2]; const float* bo = bm[3];
    float* out = (float*)d_out;

    const int M = NB * SEQ;  // 4096

    prep_half_kernel<<<1024, 256>>>(x, Wv, Wo);
    qk_mma_kernel<<<M / QK_BM, 256>>>(x, Wq, Wk, bq, bk);
    {
        dim3 grid(HID / 128, M / 128);
        gemm_mma_kernel<<<grid, 256>>>(bv, nullptr, 0);
    }
    {
        dim3 grid(SEQ / BQ, NHD, NB);
        attn_mma_kernel<<<grid, 256>>>();
    }
    {
        dim3 grid(HID / 128, M / 128);
        gemm_mma_kernel<<<grid, 256>>>(bo, out, 1);
    }
}

// round 17
// speedup vs baseline: 3.7458x; 1.0530x over previous
#include <cuda_runtime.h>
#include <cuda_fp16.h>
#include <cstdint>

#define NB   2
#define SEQ  2048
#define HID  1024
#define NHD  16
#define HDD  64

// Scratch (allocation-free rule). Referenced ONLY from device code.
__device__ uint32_t g_Qch[NB * NHD * SEQ * 4];  // [token][4 half2] (8 channels)
__device__ uint32_t g_Kch[NB * NHD * SEQ * 4];
__device__ uint32_t g_Vp[(NB * SEQ / 2) * HID]; // row-PAIR packed half2
__device__ __half   g_AttOut[NB * SEQ * HID];   // plain row-major half
__device__ __half   g_Xh[NB * SEQ * HID];       // x pre-rounded to half
__device__ __half   g_Wvh[HID * HID];           // Wv pre-rounded to half
__device__ __half   g_Woh[HID * HID];           // Wo pre-rounded to half

// ---------------------------------------------------------------------------
// helpers
// ---------------------------------------------------------------------------
__device__ __forceinline__ uint32_t pack_h2(float lo, float hi) {
    __half2 h = __floats2half2_rn(lo, hi);
    return *(uint32_t*)&h;
}
__device__ __forceinline__ void mma_f16_k16(float* d, const uint32_t* a, const uint32_t* b) {
    asm volatile(
        "mma.sync.aligned.m16n8k16.row.col.f32.f16.f16.f32 "
        "{%0,%1,%2,%3}, {%4,%5,%6,%7}, {%8,%9}, {%0,%1,%2,%3};"
        : "+f"(d[0]), "+f"(d[1]), "+f"(d[2]), "+f"(d[3])
        : "r"(a[0]), "r"(a[1]), "r"(a[2]), "r"(a[3]), "r"(b[0]), "r"(b[1]));
}
__device__ __forceinline__ void mma_f16_k8(float* d, const uint32_t* a, const uint32_t* b) {
    asm volatile(
        "mma.sync.aligned.m16n8k8.row.col.f32.f16.f16.f32 "
        "{%0,%1,%2,%3}, {%4,%5}, {%6}, {%0,%1,%2,%3};"
        : "+f"(d[0]), "+f"(d[1]), "+f"(d[2]), "+f"(d[3])
        : "r"(a[0]), "r"(a[1]), "r"(b[0]));
}
// exp on a half2 pair, x in [0, ~0.5]: degree-4 Horner in HFMA2.
// Truncation err x^5/120 <= 1.9e-4 abs; half rounding ~5e-4/step — both well
// under the 1e-3 output threshold after softmax averaging.
__device__ __forceinline__ uint32_t exp_h2(uint32_t xu) {
    __half2 x = *(__half2*)&xu;
    const __half2 c4 = __float2half2_rn(0.041666667f);
    const __half2 c3 = __float2half2_rn(0.16666667f);
    const __half2 c2 = __float2half2_rn(0.5f);
    const __half2 c1 = __float2half2_rn(1.0f);
    __half2 h = __hfma2(x, c4, c3);
    h = __hfma2(h, x, c2);
    h = __hfma2(h, x, c1);
    h = __hfma2(h, x, c1);
    return *(uint32_t*)&h;
}
// fp32 exp (used only in qk epilogue path via expf; kept for clarity)
__device__ __forceinline__ float exp_pos(float x) {
    return 1.0f + x * (1.0f + x * (0.5f + x * (0.16666667f
           + x * (0.041666667f + x * 0.0083333333f))));
}
__device__ __forceinline__ uint32_t smem_u32(const void* p) {
    uint32_t a;
    asm("{ .reg .u64 t; cvta.to.shared.u64 t, %1; cvt.u32.u64 %0, t; }" : "=r"(a) : "l"(p));
    return a;
}
__device__ __forceinline__ void cp16(uint32_t dst, const void* src) {
    asm volatile("cp.async.ca.shared.global [%0], [%1], 16;" :: "r"(dst), "l"(src));
}
#define CP_COMMIT() asm volatile("cp.async.commit_group;" ::: "memory")
#define CP_WAIT(n)  asm volatile("cp.async.wait_group %0;" :: "n"(n) : "memory")

// ---------------------------------------------------------------------------
// Kernel 0: pre-round x, Wv, Wo to half (enables raw cp.async GEMM staging).
// ---------------------------------------------------------------------------
__global__ __launch_bounds__(256) void prep_half_kernel(
    const float* __restrict__ x, const float* __restrict__ Wv, const float* __restrict__ Wo)
{
    const int n1 = NB * SEQ * HID / 4;
    const int n2 = HID * HID / 4;
    const int total = n1 + 2 * n2;
    for (int i = blockIdx.x * 256 + threadIdx.x; i < total; i += gridDim.x * 256) {
        const float4* src;
        uint2* dst;
        if (i < n1)           { src = (const float4*)x  + i;             dst = (uint2*)g_Xh  + i; }
        else if (i < n1 + n2) { src = (const float4*)Wv + (i - n1);      dst = (uint2*)g_Wvh + (i - n1); }
        else                  { src = (const float4*)Wo + (i - n1 - n2); dst = (uint2*)g_Woh + (i - n1 - n2); }
        float4 v = *src;
        *dst = make_uint2(pack_h2(v.x, v.y), pack_h2(v.z, v.w));
    }
}

// ---------------------------------------------------------------------------
// Kernel 1: QK projection as fp16 mma GEMM + tetra-channel epilogue.
// (verified ~12 us; unchanged)
// ---------------------------------------------------------------------------
#define QK_BM 32

__global__ __launch_bounds__(256) void qk_mma_kernel(
    const float* __restrict__ x,
    const float* __restrict__ Wq, const float* __restrict__ Wk,
    const float* __restrict__ bq, const float* __restrict__ bk)
{
    __shared__ uint32_t As[QK_BM][36];
    __shared__ uint32_t Ws[64][36];

    const int tid  = threadIdx.x;
    const int lane = tid & 31;
    const int wid  = tid >> 5;
    const int gid  = lane >> 2;
    const int tig  = lane & 3;
    const int bm   = blockIdx.x * QK_BM;
    const int wm   = (wid & 1) * 16;
    const int wn   = (wid >> 1) * 16;

    float c[2][4];
    #pragma unroll
    for (int nt = 0; nt < 2; nt++)
        #pragma unroll
        for (int k = 0; k < 4; k++) c[nt][k] = 0.0f;

    for (int kc = 0; kc < HID; kc += 64) {
        __syncthreads();
        #pragma unroll
        for (int i = 0; i < 2; i++) {
            int idx = tid + i * 256;
            int row = idx >> 4;
            int c8  = idx & 15;
            float4 v = *(const float4*)&x[(size_t)(bm + row) * HID + kc + c8 * 4];
            *(uint2*)&As[row][c8 * 2] = make_uint2(pack_h2(v.x, v.y), pack_h2(v.z, v.w));
        }
        #pragma unroll
        for (int i = 0; i < 4; i++) {
            int idx = tid + i * 256;
            int row = idx >> 4;           // dot index 0..63
            int c8  = idx & 15;
            int qk   = row >> 5;
            int dd   = row & 31;
            int h    = dd >> 1;
            int slot = (dd & 1) * 2;
            const float* Wr = (qk ? Wk : Wq) + (size_t)(h * HDD + slot) * HID;
            float4 v = *(const float4*)&Wr[kc + c8 * 4];
            *(uint2*)&Ws[row][c8 * 2] = make_uint2(pack_h2(v.x, v.y), pack_h2(v.z, v.w));
        }
        __syncthreads();

        #pragma unroll
        for (int ks2 = 0; ks2 < 32; ks2 += 8) {
            uint32_t af[4];
            int r0 = wm + gid;
            af[0] = As[r0][ks2 + tig];
            af[1] = As[r0 + 8][ks2 + tig];
            af[2] = As[r0][ks2 + tig + 4];
            af[3] = As[r0 + 8][ks2 + tig + 4];
            #pragma unroll
            for (int nt = 0; nt < 2; nt++) {
                int n0 = wn + nt * 8 + gid;
                uint32_t bf[2];
                bf[0] = Ws[n0][ks2 + tig];
                bf[1] = Ws[n0][ks2 + tig + 4];
                mma_f16_k16(c[nt], af, bf);
            }
        }
    }

    #pragma unroll
    for (int nt = 0; nt < 2; nt++) {
        int col0 = wn + nt * 8 + 2 * tig;
        int qk = col0 >> 5;
        int dd = col0 & 31;
        int h  = dd >> 1;
        const float* bb = qk ? bk : bq;
        float b0 = bb[h * HDD + 0];
        float b1 = bb[h * HDD + 2];
        float sc0 = (qk == 0) ? 0.125f : 1.0f;
        float sc1 = (qk == 0) ? 0.1f   : 1.0f;
        #pragma unroll
        for (int hf = 0; hf < 2; hf++) {
            int m = bm + wm + gid + hf * 8;
            float t0 = c[nt][hf * 2 + 0] + b0;
            float t1 = c[nt][hf * 2 + 1] + b1;

            float a0 = 1.0f / (1.0f + expf(-t0));
            float na0 = 1.0f - a0;
            float nei0 = fminf(fmaxf(1.0f - (a0 + na0), 0.0f), 1.0f);
            float a1 = 1.0f / (1.0f + expf(-t1));
            float na1 = 1.0f - a1;
            float nei1 = fminf(fmaxf(1.0f - (a1 + na1), 0.0f), 1.0f);

            uint4 out;
            out.x = pack_h2(a0 * sc0, na0 * sc0);
            out.y = pack_h2(a0 * na0 * sc0, nei0 * sc0);
            out.z = pack_h2(a1 * sc1, na1 * sc1);
            out.w = pack_h2(a1 * na1 * sc1, nei1 * sc1);

            int b_ = m / SEQ;
            int s_ = m % SEQ;
            uint32_t* dst = (qk ? g_Kch : g_Qch) + ((size_t)(b_ * NHD + h) * SEQ + s_) * 4;
            *(uint4*)dst = out;
        }
    }
}

// ---------------------------------------------------------------------------
// Kernel 2/4: fp16 mma GEMM, cp.async double-buffered (verified R15).
// mode 0: A = g_Xh,    W = g_Wvh, C -> g_Vp row-pair half2.
// mode 1: A = g_AttOut, W = g_Woh, C -> Cout fp32.
// ---------------------------------------------------------------------------
__global__ __launch_bounds__(256) void gemm_mma_kernel(
    const float* __restrict__ bias, float* __restrict__ Cout, int mode)
{
    __shared__ __align__(16) uint32_t As[2][128][20];
    __shared__ __align__(16) uint32_t Bs[2][128][20];

    const __half* A = (mode == 0) ? g_Xh  : g_AttOut;
    const __half* W = (mode == 0) ? g_Wvh : g_Woh;

    const int tid  = threadIdx.x;
    const int lane = tid & 31;
    const int wid  = tid >> 5;
    const int bm   = blockIdx.y * 128;
    const int bn   = blockIdx.x * 128;
    const int wm   = (wid & 1) * 64;
    const int wn   = (wid >> 1) * 32;
    const int gid  = lane >> 2;
    const int tig  = lane & 3;

    const uint32_t sA = smem_u32(As);
    const uint32_t sB = smem_u32(Bs);

    float c[4][4][4];
    #pragma unroll
    for (int mt = 0; mt < 4; mt++)
        #pragma unroll
        for (int nt = 0; nt < 4; nt++)
            #pragma unroll
            for (int k = 0; k < 4; k++) c[mt][nt][k] = 0.0f;

    // prologue: stage chunk 0 into buffer 0
    #pragma unroll
    for (int i = 0; i < 2; i++) {
        int idx = tid + i * 256;
        int row = idx >> 2;
        int q   = idx & 3;
        cp16(sA + (uint32_t)(row * 80 + q * 16), A + (size_t)(bm + row) * HID + q * 8);
        cp16(sB + (uint32_t)(row * 80 + q * 16), W + (size_t)(bn + row) * HID + q * 8);
    }
    CP_COMMIT();

    const int NCH = HID / 32;   // 32 chunks
    for (int ch = 0; ch < NCH; ch++) {
        const int buf = ch & 1;
        const bool more = (ch + 1 < NCH);
        if (more) {
            const int nb = buf ^ 1;
            const int kc = (ch + 1) * 32;
            #pragma unroll
            for (int i = 0; i < 2; i++) {
                int idx = tid + i * 256;
                int row = idx >> 2;
                int q   = idx & 3;
                cp16(sA + (uint32_t)(nb * 10240 + row * 80 + q * 16),
                     A + (size_t)(bm + row) * HID + kc + q * 8);
                cp16(sB + (uint32_t)(nb * 10240 + row * 80 + q * 16),
                     W + (size_t)(bn + row) * HID + kc + q * 8);
            }
            CP_COMMIT();
            CP_WAIT(1);
        } else {
            CP_WAIT(0);
        }
        __syncthreads();

        #pragma unroll
        for (int ks2 = 0; ks2 < 16; ks2 += 8) {
            uint32_t af[4][4];
            #pragma unroll
            for (int mt = 0; mt < 4; mt++) {
                int r0 = wm + mt * 16 + gid;
                af[mt][0] = As[buf][r0][ks2 + tig];
                af[mt][1] = As[buf][r0 + 8][ks2 + tig];
                af[mt][2] = As[buf][r0][ks2 + tig + 4];
                af[mt][3] = As[buf][r0 + 8][ks2 + tig + 4];
            }
            uint32_t bf[4][2];
            #pragma unroll
            for (int nt = 0; nt < 4; nt++) {
                int n0 = wn + nt * 8 + gid;
                bf[nt][0] = Bs[buf][n0][ks2 + tig];
                bf[nt][1] = Bs[buf][n0][ks2 + tig + 4];
            }
            #pragma unroll
            for (int mt = 0; mt < 4; mt++)
                #pragma unroll
                for (int nt = 0; nt < 4; nt++)
                    mma_f16_k16(c[mt][nt], af[mt], bf[nt]);
        }
        __syncthreads();
    }

    if (mode == 0) {
        // pack row-pairs (2p, 2p+1) into half2 for attention's V B-fragments
        #pragma unroll
        for (int mt = 0; mt < 4; mt++) {
            int rbase = bm + wm + mt * 16 + (gid & ~1);
            int p0 = rbase >> 1;
            #pragma unroll
            for (int nt = 0; nt < 4; nt++) {
                int col0 = bn + wn + nt * 8 + 2 * tig;
                float b0 = bias[col0], b1 = bias[col0 + 1];
                float v0 = c[mt][nt][0] + b0;
                float v1 = c[mt][nt][1] + b1;
                float v2 = c[mt][nt][2] + b0;
                float v3 = c[mt][nt][3] + b1;
                float o0 = __shfl_xor_sync(0xffffffffu, v0, 4);
                float o1 = __shfl_xor_sync(0xffffffffu, v1, 4);
                float o2 = __shfl_xor_sync(0xffffffffu, v2, 4);
                float o3 = __shfl_xor_sync(0xffffffffu, v3, 4);
                if ((gid & 1) == 0) {
                    g_Vp[(size_t)p0 * HID + col0]       = pack_h2(v0, o0);
                    g_Vp[(size_t)(p0 + 4) * HID + col0] = pack_h2(v2, o2);
                } else {
                    g_Vp[(size_t)p0 * HID + col0 + 1]       = pack_h2(o1, v1);
                    g_Vp[(size_t)(p0 + 4) * HID + col0 + 1] = pack_h2(o3, v3);
                }
            }
        }
    } else {
        #pragma unroll
        for (int mt = 0; mt < 4; mt++) {
            int row0 = bm + wm + mt * 16 + gid;
            #pragma unroll
            for (int nt = 0; nt < 4; nt++) {
                int col0 = bn + wn + nt * 8 + 2 * tig;
                float b0 = bias[col0], b1 = bias[col0 + 1];
                float2 v0; v0.x = c[mt][nt][0] + b0; v0.y = c[mt][nt][1] + b1;
                float2 v1; v1.x = c[mt][nt][2] + b0; v1.y = c[mt][nt][3] + b1;
                *(float2*)&Cout[(size_t)row0 * HID + col0] = v0;
                *(float2*)&Cout[(size_t)(row0 + 8) * HID + col0] = v1;
            }
        }
    }
}

// ---------------------------------------------------------------------------
// Kernel 3: fp16 attention, register-resident P, half2 exp.
// Scores packed to half2 straight out of the S-mma; exp runs in HFMA2 and its
// output IS the O-phase A-fragment (zero packs in O phase). z accumulated in
// half2 per tile, flushed to fp32 once per tile.
// ---------------------------------------------------------------------------
#define BQ 128
#define BK 64

__global__ __launch_bounds__(256) void attn_mma_kernel()
{
    __shared__ __align__(16) uint32_t Qs[BQ][4];
    __shared__ __align__(16) uint32_t Ks[2][BK][4];
    __shared__ __align__(16) uint32_t Vs[2][BK / 2][72];

    const int tid  = threadIdx.x;
    const int lane = tid & 31;
    const int wid  = tid >> 5;
    const int gid  = lane >> 2;
    const int tig  = lane & 3;
    const int q0   = blockIdx.x * BQ;
    const int h    = blockIdx.y;
    const int b    = blockIdx.z;

    const uint32_t* Qg = g_Qch + ((size_t)(b * NHD + h) * SEQ + q0) * 4;
    const uint32_t* Kg = g_Kch + ((size_t)(b * NHD + h) * SEQ) * 4;
    const uint32_t* Vg = g_Vp + (size_t)b * (SEQ / 2) * HID + h * HDD;

    const uint32_t sK = smem_u32(Ks);
    const uint32_t sV = smem_u32(Vs);

    // stage Q tile (128 tokens x 4 half2 = 512 u32)
    ((uint32_t*)Qs)[tid]       = Qg[tid];
    ((uint32_t*)Qs)[tid + 256] = Qg[tid + 256];

    // prologue: stage tile 0 into buffer 0
    #pragma unroll
    for (int i = 0; i < 2; i++) {
        int idx = tid + i * 256;
        int t2  = idx >> 4;
        int q   = idx & 15;
        cp16(sV + (uint32_t)(t2 * 288 + q * 16), Vg + (size_t)t2 * HID + q * 4);
    }
    if (tid < BK)
        cp16(sK + (uint32_t)(tid * 16), Kg + (size_t)tid * 4);
    CP_COMMIT();
    __syncthreads();

    // Q A-fragment (m16n8k8: 2 regs), rows 16*wid + {gid, gid+8}
    uint32_t aq[2];
    aq[0] = Qs[wid * 16 + gid][tig];
    aq[1] = Qs[wid * 16 + gid + 8][tig];

    float o[8][4];
    #pragma unroll
    for (int nt = 0; nt < 8; nt++)
        #pragma unroll
        for (int k = 0; k < 4; k++) o[nt][k] = 0.0f;
    float zacc0 = 0.0f, zacc1 = 0.0f;

    const __half2 h2zero = __float2half2_rn(0.0f);

    const int NT = SEQ / BK;   // 32 tiles
    for (int it = 0; it < NT; it++) {
        const int buf = it & 1;
        const bool more = (it + 1 < NT);
        if (more) {
            const int nb = buf ^ 1;
            const int kt = (it + 1) * BK;
            #pragma unroll
            for (int i = 0; i < 2; i++) {
                int idx = tid + i * 256;
                int t2  = idx >> 4;
                int q   = idx & 15;
                cp16(sV + (uint32_t)(nb * 9216 + t2 * 288 + q * 16),
                     Vg + (size_t)(kt / 2 + t2) * HID + q * 4);
            }
            if (tid < BK)
                cp16(sK + (uint32_t)(nb * 1024 + tid * 16), Kg + (size_t)(kt + tid) * 4);
            CP_COMMIT();
            CP_WAIT(1);
        } else {
            CP_WAIT(0);
        }
        __syncthreads();

        // ---- S phase: rows 16w..16w+15 x all 64 keys = 8 n-tiles ----
        // eh[j][0] = exp half2 of (row gid, cols 2tig,2tig+1) for n-tile j
        // eh[j][1] = exp half2 of (row gid+8, same cols)
        uint32_t eh[8][2];
        __half2 zh0 = h2zero, zh1 = h2zero;
        #pragma unroll
        for (int j = 0; j < 8; j++) {
            uint32_t bk_ = Ks[buf][j * 8 + gid][tig];
            float c[4] = {0.f, 0.f, 0.f, 0.f};
            mma_f16_k8(c, aq, &bk_);
            uint32_t e01 = exp_h2(pack_h2(c[0], c[1]));
            uint32_t e23 = exp_h2(pack_h2(c[2], c[3]));
            eh[j][0] = e01;
            eh[j][1] = e23;
            zh0 = __hadd2(zh0, *(__half2*)&e01);
            zh1 = __hadd2(zh1, *(__half2*)&e23);
        }
        // flush z partials to fp32 (once per tile)
        zacc0 += __half2float(__low2half(zh0)) + __half2float(__high2half(zh0));
        zacc1 += __half2float(__low2half(zh1)) + __half2float(__high2half(zh1));

        // ---- O phase: P(16x64) @ V(64x64); A-fragments ARE the eh regs ----
        #pragma unroll
        for (int kk = 0; kk < 4; kk++) {
            uint32_t ap[4];
            ap[0] = eh[2 * kk][0];
            ap[1] = eh[2 * kk][1];
            ap[2] = eh[2 * kk + 1][0];
            ap[3] = eh[2 * kk + 1][1];
            const int k2 = kk * 8;
            #pragma unroll
            for (int nt = 0; nt < 8; nt++) {
                int n0 = nt * 8 + gid;
                uint32_t bv[2];
                bv[0] = Vs[buf][k2 + tig][n0];
                bv[1] = Vs[buf][k2 + tig + 4][n0];
                mma_f16_k16(o[nt], ap, bv);
            }
        }
        __syncthreads();   // compute done before this buf is restaged next iter
    }

    // ---- Z reduction: butterfly over the 4-lane tig group ----
    zacc0 += __shfl_xor_sync(0xffffffffu, zacc0, 1);
    zacc0 += __shfl_xor_sync(0xffffffffu, zacc0, 2);
    zacc1 += __shfl_xor_sync(0xffffffffu, zacc1, 1);
    zacc1 += __shfl_xor_sync(0xffffffffu, zacc1, 2);
    const float inv0 = 1.0f / zacc0;
    const float inv1 = 1.0f / zacc1;

    // ---- normalize + store (half, row-major for GEMM-1) ----
    uint32_t* Og = (uint32_t*)g_AttOut;   // half2 view, HID/2 per row
    const size_t r0 = (size_t)(b * SEQ + q0 + wid * 16 + gid);
    const int cbase = (h * HDD) >> 1;
    #pragma unroll
    for (int nt = 0; nt < 8; nt++) {
        int cc2 = cbase + nt * 4 + tig;
        Og[r0 * (HID / 2) + cc2]       = pack_h2(o[nt][0] * inv0, o[nt][1] * inv0);
        Og[(r0 + 8) * (HID / 2) + cc2] = pack_h2(o[nt][2] * inv1, o[nt][3] * inv1);
    }
}

// ---------------------------------------------------------------------------
extern "C" void kernel_launch(void* const* d_in, const int* in_sizes, int n_in,
                              void* d_out, int out_size)
{
    const float* x = nullptr;
    const float* Wm[4] = {nullptr, nullptr, nullptr, nullptr};
    const float* bm[4] = {nullptr, nullptr, nullptr, nullptr};
    int wi = 0, bi = 0;
    for (int i = 0; i < n_in; i++) {
        if (in_sizes[i] == NB * SEQ * HID)      x = (const float*)d_in[i];
        else if (in_sizes[i] == HID * HID) { if (wi < 4) Wm[wi++] = (const float*)d_in[i]; }
        else if (in_sizes[i] == HID)       { if (bi < 4) bm[bi++] = (const float*)d_in[i]; }
    }
    const float* Wq = Wm[0]; const float* Wk = Wm[1];
    const float* Wv = Wm[2]; const float* Wo = Wm[3];
    const float* bq = bm[0]; const float* bk = bm[1];
    const float* bv = bm[2]; const float* bo = bm[3];
    float* out = (float*)d_out;

    const int M = NB * SEQ;  // 4096

    prep_half_kernel<<<1024, 256>>>(x, Wv, Wo);
    qk_mma_kernel<<<M / QK_BM, 256>>>(x, Wq, Wk, bq, bk);
    {
        dim3 grid(HID / 128, M / 128);
        gemm_mma_kernel<<<grid, 256>>>(bv, nullptr, 0);
    }
    {
        dim3 grid(SEQ / BQ, NHD, NB);
        attn_mma_kernel<<<grid, 256>>>();
    }
    {
        dim3 grid(HID / 128, M / 128);
        gemm_mma_kernel<<<grid, 256>>>(bo, out, 1);
    }
}